// round 8
// baseline (speedup 1.0000x reference)
#include <cuda_runtime.h>
#include <cuda_bf16.h>
#include <cuda_fp16.h>
#include <cstdint>

#define NN 10000
#define NE 320000
#define F_HID 256

// ---------------- scratch (device globals; no allocation allowed) ----------------
__device__ int   g_deg[NN];
__device__ int   g_incnt[NN];
__device__ int   g_roff[NN];                        // CSR bucket start (order-free alloc)
__device__ int   g_rend[NN];                        // CSR bucket end
__device__ int   g_rank[NE];
__device__ int   g_total;
__device__ float g_inv[NN];
__device__ int2  g_csr[NE];                         // (src, w bits)
__device__ __align__(16) __half g_x16[NN * F_HID];  // fp16 gather operand
__device__ __nv_bfloat16 g_ahi[NN * F_HID];
__device__ __nv_bfloat16 g_alo[NN * F_HID];
__device__ __nv_bfloat16 g_whi[256 * 256 * 3];
__device__ __nv_bfloat16 g_wlo[256 * 256 * 3];
__device__ float g_vsum;
__device__ float g_dotp;   // b3 . Wp
__device__ float g_dotv;   // b3 . Wv

// ---------------- helpers ----------------
__device__ __forceinline__ void cvt_hilo2(float x0, float x1, uint32_t& hip, uint32_t& lop) {
    __nv_bfloat162 h = __floats2bfloat162_rn(x0, x1);
    float h0 = __bfloat162float(__low2bfloat16(h));
    float h1 = __bfloat162float(__high2bfloat16(h));
    __nv_bfloat162 l = __floats2bfloat162_rn(x0 - h0, x1 - h1);
    hip = *reinterpret_cast<uint32_t*>(&h);
    lop = *reinterpret_cast<uint32_t*>(&l);
}

__device__ __forceinline__ void ldsm4(uint32_t* r, uint32_t addr) {
    asm volatile("ldmatrix.sync.aligned.m8n8.x4.shared.b16 {%0,%1,%2,%3}, [%4];"
                 : "=r"(r[0]), "=r"(r[1]), "=r"(r[2]), "=r"(r[3]) : "r"(addr));
}
__device__ __forceinline__ void ldsm4t(uint32_t* r, uint32_t addr) {
    asm volatile("ldmatrix.sync.aligned.m8n8.x4.trans.shared.b16 {%0,%1,%2,%3}, [%4];"
                 : "=r"(r[0]), "=r"(r[1]), "=r"(r[2]), "=r"(r[3]) : "r"(addr));
}
__device__ __forceinline__ void mma16816(float* c, const uint32_t* a, const uint32_t* b) {
    asm volatile(
        "mma.sync.aligned.m16n8k16.row.col.f32.bf16.bf16.f32 "
        "{%0,%1,%2,%3}, {%4,%5,%6,%7}, {%8,%9}, {%0,%1,%2,%3};"
        : "+f"(c[0]), "+f"(c[1]), "+f"(c[2]), "+f"(c[3])
        : "r"(a[0]), "r"(a[1]), "r"(a[2]), "r"(a[3]), "r"(b[0]), "r"(b[1]));
}

// ---------------- graph preprocessing ----------------
__global__ void zero_kernel() {
    int i = blockIdx.x * blockDim.x + threadIdx.x;
    if (i < NN) { g_deg[i] = 0; g_incnt[i] = 0; }
    if (i == 0) { g_vsum = 0.0f; g_total = 0; }
}

__global__ void count_kernel(const int* __restrict__ src, const int* __restrict__ dst) {
    int e = blockIdx.x * blockDim.x + threadIdx.x;
    if (e < NE) {
        atomicAdd(&g_deg[src[e]], 1);
        g_rank[e] = atomicAdd(&g_incnt[dst[e]], 1);
    }
}

// order-free CSR bucket allocation
__global__ void alloc_kernel() {
    int i = blockIdx.x * blockDim.x + threadIdx.x;
    if (i < NN) {
        int c = g_incnt[i];
        int base = atomicAdd(&g_total, c);
        g_roff[i] = base;
        g_rend[i] = base + c;
        int d = g_deg[i];
        g_inv[i] = (d > 0) ? 1.0f / (float)d : 0.0f;
    }
}

__global__ void fill_kernel(const int* __restrict__ src, const int* __restrict__ dst) {
    int e = blockIdx.x * blockDim.x + threadIdx.x;
    if (e < NE) {
        int d = dst[e];
        int s = src[e];
        int p = g_roff[d] + g_rank[e];
        g_csr[p] = make_int2(s, __float_as_int(g_inv[s]));
    }
}

// ---------------- head constants + output init ----------------
__global__ void dots_kernel(const float* __restrict__ b3, const float* __restrict__ Wp,
                            const float* __restrict__ Wv) {
    __shared__ float sp[8], sv[8];
    int t = threadIdx.x;  // 256
    float pd = b3[t] * Wp[t];
    float pv = b3[t] * Wv[t];
    #pragma unroll
    for (int o = 16; o > 0; o >>= 1) {
        pd += __shfl_xor_sync(0xffffffffu, pd, o);
        pv += __shfl_xor_sync(0xffffffffu, pv, o);
    }
    if ((t & 31) == 0) { sp[t >> 5] = pd; sv[t >> 5] = pv; }
    __syncthreads();
    if (t == 0) {
        float a = 0.f, b = 0.f;
        #pragma unroll
        for (int w = 0; w < 8; w++) { a += sp[w]; b += sv[w]; }
        g_dotp = a; g_dotv = b;
    }
}

__global__ void init_out(const float* __restrict__ bp, float* __restrict__ out) {
    int i = blockIdx.x * blockDim.x + threadIdx.x;
    if (i < NN) out[i] = bp[0] + g_dotp;
}

// ---------------- fused conversions ----------------
#define NFP (NN * 128 / 2)
#define W1P (128 * 256 / 2)
#define W2P (256 * 256 / 2)
__global__ void convert_all(const float* __restrict__ X, const float* __restrict__ W1,
                            const float* __restrict__ W2, const float* __restrict__ W3) {
    int t = blockIdx.x * blockDim.x + threadIdx.x;
    if (t < NFP) {
        float2 v = *(const float2*)(X + 2 * t);
        __half2 h = __floats2half2_rn(v.x, v.y);
        *(uint32_t*)((char*)g_x16 + 4 * t) = *reinterpret_cast<uint32_t*>(&h);
        return;
    }
    int u = t - NFP;
    const float* Wsrc;
    int off;
    if (u < W1P) { Wsrc = W1; off = 0; }
    else if (u < W1P + W2P) { Wsrc = W2; off = 32768; u -= W1P; }
    else if (u < W1P + 2 * W2P) { Wsrc = W3; off = 98304; u -= W1P + W2P; }
    else return;
    float2 v = *(const float2*)(Wsrc + 2 * u);
    uint32_t hip, lop;
    cvt_hilo2(v.x, v.y, hip, lop);
    *(uint32_t*)((char*)g_whi + 2 * (off + 2 * u)) = hip;
    *(uint32_t*)((char*)g_wlo + 2 * (off + 2 * u)) = lop;
}

// ---------------- edge aggregation (fp16 gather, fp32 accum, MLP=4) -> bf16 hi/lo ----------------
template <int CHUNKS>  // 1: F=128, 2: F=256
__global__ void aggregate_kernel(const __half* __restrict__ X,
                                 __nv_bfloat16* __restrict__ Yhi,
                                 __nv_bfloat16* __restrict__ Ylo, int F) {
    int gw    = (blockIdx.x * blockDim.x + threadIdx.x) >> 5;
    int lane  = threadIdx.x & 31;
    int nwrp  = (gridDim.x * blockDim.x) >> 5;
    for (int n = gw; n < NN; n += nwrp) {
        int s0 = g_roff[n], s1 = g_rend[n];
        float4 acc0 = make_float4(0.f, 0.f, 0.f, 0.f);
        float4 acc1 = make_float4(0.f, 0.f, 0.f, 0.f);
        for (int e0 = s0; e0 < s1; e0 += 32) {
            int   ss = 0; float ww = 0.f;
            if (e0 + lane < s1) {
                int2 ev = g_csr[e0 + lane];
                ss = ev.x; ww = __int_as_float(ev.y);
            }
            int cnt = min(32, s1 - e0);
            int j = 0;
            for (; j + 4 <= cnt; j += 4) {
                int sj0 = __shfl_sync(0xffffffffu, ss, j);
                int sj1 = __shfl_sync(0xffffffffu, ss, j + 1);
                int sj2 = __shfl_sync(0xffffffffu, ss, j + 2);
                int sj3 = __shfl_sync(0xffffffffu, ss, j + 3);
                float w0 = __shfl_sync(0xffffffffu, ww, j);
                float w1 = __shfl_sync(0xffffffffu, ww, j + 1);
                float w2 = __shfl_sync(0xffffffffu, ww, j + 2);
                float w3 = __shfl_sync(0xffffffffu, ww, j + 3);
                if (CHUNKS == 1) {
                    uint2 v0 = ((const uint2*)(X + (size_t)sj0 * F))[lane];
                    uint2 v1 = ((const uint2*)(X + (size_t)sj1 * F))[lane];
                    uint2 v2 = ((const uint2*)(X + (size_t)sj2 * F))[lane];
                    uint2 v3 = ((const uint2*)(X + (size_t)sj3 * F))[lane];
                    #define ACC2(vv, wj) { \
                        float2 f0 = __half22float2(*reinterpret_cast<__half2*>(&(vv).x)); \
                        float2 f1 = __half22float2(*reinterpret_cast<__half2*>(&(vv).y)); \
                        acc0.x += (wj) * f0.x; acc0.y += (wj) * f0.y; \
                        acc0.z += (wj) * f1.x; acc0.w += (wj) * f1.y; }
                    ACC2(v0, w0) ACC2(v1, w1) ACC2(v2, w2) ACC2(v3, w3)
                    #undef ACC2
                } else {
                    uint4 v0 = ((const uint4*)(X + (size_t)sj0 * F))[lane];
                    uint4 v1 = ((const uint4*)(X + (size_t)sj1 * F))[lane];
                    uint4 v2 = ((const uint4*)(X + (size_t)sj2 * F))[lane];
                    uint4 v3 = ((const uint4*)(X + (size_t)sj3 * F))[lane];
                    #define ACC4(vv, wj) { \
                        float2 f0 = __half22float2(*reinterpret_cast<__half2*>(&(vv).x)); \
                        float2 f1 = __half22float2(*reinterpret_cast<__half2*>(&(vv).y)); \
                        float2 f2 = __half22float2(*reinterpret_cast<__half2*>(&(vv).z)); \
                        float2 f3 = __half22float2(*reinterpret_cast<__half2*>(&(vv).w)); \
                        acc0.x += (wj) * f0.x; acc0.y += (wj) * f0.y; \
                        acc0.z += (wj) * f1.x; acc0.w += (wj) * f1.y; \
                        acc1.x += (wj) * f2.x; acc1.y += (wj) * f2.y; \
                        acc1.z += (wj) * f3.x; acc1.w += (wj) * f3.y; }
                    ACC4(v0, w0) ACC4(v1, w1) ACC4(v2, w2) ACC4(v3, w3)
                    #undef ACC4
                }
            }
            for (; j < cnt; j++) {
                int   sj = __shfl_sync(0xffffffffu, ss, j);
                float wj = __shfl_sync(0xffffffffu, ww, j);
                if (CHUNKS == 1) {
                    uint2 v = ((const uint2*)(X + (size_t)sj * F))[lane];
                    float2 f0 = __half22float2(*reinterpret_cast<__half2*>(&v.x));
                    float2 f1 = __half22float2(*reinterpret_cast<__half2*>(&v.y));
                    acc0.x += wj * f0.x; acc0.y += wj * f0.y;
                    acc0.z += wj * f1.x; acc0.w += wj * f1.y;
                } else {
                    uint4 v = ((const uint4*)(X + (size_t)sj * F))[lane];
                    float2 f0 = __half22float2(*reinterpret_cast<__half2*>(&v.x));
                    float2 f1 = __half22float2(*reinterpret_cast<__half2*>(&v.y));
                    float2 f2 = __half22float2(*reinterpret_cast<__half2*>(&v.z));
                    float2 f3 = __half22float2(*reinterpret_cast<__half2*>(&v.w));
                    acc0.x += wj * f0.x; acc0.y += wj * f0.y;
                    acc0.z += wj * f1.x; acc0.w += wj * f1.y;
                    acc1.x += wj * f2.x; acc1.y += wj * f2.y;
                    acc1.z += wj * f3.x; acc1.w += wj * f3.y;
                }
            }
        }
        uint32_t h01, l01, h23, l23;
        cvt_hilo2(acc0.x, acc0.y, h01, l01);
        cvt_hilo2(acc0.z, acc0.w, h23, l23);
        if (CHUNKS == 1) {
            ((uint2*)(Yhi + (size_t)n * F))[lane] = make_uint2(h01, h23);
            ((uint2*)(Ylo + (size_t)n * F))[lane] = make_uint2(l01, l23);
        } else {
            uint32_t h45, l45, h67, l67;
            cvt_hilo2(acc1.x, acc1.y, h45, l45);
            cvt_hilo2(acc1.z, acc1.w, h67, l67);
            ((uint4*)(Yhi + (size_t)n * F))[lane] = make_uint4(h01, h23, h45, h67);
            ((uint4*)(Ylo + (size_t)n * F))[lane] = make_uint4(l01, l23, l45, l67);
        }
    }
}

// ---------------- GEMM via mma.sync bf16 hi/lo ----------------
// CTA tile 160x128, 8 warps (2m x 4n), warp tile 80x32, BK=32 -> 126 CTAs (single wave)
// mode 0: relu + fp16 out (C16)
// mode 1: fused heads epilogue: atomicAdd PI partials into out, V partials into g_vsum
#define MT 160
#define AS_STRIDE 40
#define BS_STRIDE 136
__global__ void __launch_bounds__(256)
gemm_mma(const __nv_bfloat16* __restrict__ Ahi, const __nv_bfloat16* __restrict__ Alo,
         const __nv_bfloat16* __restrict__ Whi, const __nv_bfloat16* __restrict__ Wlo,
         const float* __restrict__ bias, __half* __restrict__ C16,
         const float* __restrict__ Wp, const float* __restrict__ Wv,
         float* __restrict__ out, int K, int mode) {
    __shared__ __align__(16) __nv_bfloat16 sAhi[MT * AS_STRIDE];
    __shared__ __align__(16) __nv_bfloat16 sAlo[MT * AS_STRIDE];
    __shared__ __align__(16) __nv_bfloat16 sBhi[32 * BS_STRIDE];
    __shared__ __align__(16) __nv_bfloat16 sBlo[32 * BS_STRIDE];
    __shared__ float sbias[128];
    __shared__ float spi[MT];
    __shared__ float svred[8];

    int tid = threadIdx.x;
    int m0 = blockIdx.x * MT, n0 = blockIdx.y * 128;
    if (tid < 128) sbias[tid] = bias[n0 + tid];
    int wid = tid >> 5, lane = tid & 31;
    int wm = (wid & 1) * 80, wn = (wid >> 1) * 32;

    float acc[5][4][4];
    #pragma unroll
    for (int i = 0; i < 5; i++)
        #pragma unroll
        for (int j = 0; j < 4; j++)
            #pragma unroll
            for (int q = 0; q < 4; q++) acc[i][j][q] = 0.f;

    const uint4 z4 = make_uint4(0, 0, 0, 0);

    for (int kc = 0; kc < K; kc += 32) {
        #pragma unroll
        for (int idx = tid; idx < MT * 4; idx += 256) {
            int row = idx >> 2, c16 = idx & 3;
            int gr = m0 + row;
            uint4 vh = z4, vl = z4;
            if (gr < NN) {
                vh = *(const uint4*)(Ahi + (size_t)gr * K + kc + c16 * 8);
                vl = *(const uint4*)(Alo + (size_t)gr * K + kc + c16 * 8);
            }
            *(uint4*)(sAhi + row * AS_STRIDE + c16 * 8) = vh;
            *(uint4*)(sAlo + row * AS_STRIDE + c16 * 8) = vl;
        }
        #pragma unroll
        for (int idx = tid; idx < 512; idx += 256) {
            int row = idx >> 4, c16 = idx & 15;
            *(uint4*)(sBhi + row * BS_STRIDE + c16 * 8) =
                *(const uint4*)(Whi + (size_t)(kc + row) * 256 + n0 + c16 * 8);
            *(uint4*)(sBlo + row * BS_STRIDE + c16 * 8) =
                *(const uint4*)(Wlo + (size_t)(kc + row) * 256 + n0 + c16 * 8);
        }
        __syncthreads();

        #pragma unroll
        for (int k16 = 0; k16 < 2; k16++) {
            uint32_t ah[5][4], al[5][4], bh[4][2], bl[4][2];
            #pragma unroll
            for (int mt = 0; mt < 5; mt++) {
                int row = wm + mt * 16 + (lane & 15);
                int col = k16 * 16 + (lane >> 4) * 8;
                uint32_t ad = (uint32_t)__cvta_generic_to_shared(sAhi + row * AS_STRIDE + col);
                ldsm4(ah[mt], ad);
                ad = (uint32_t)__cvta_generic_to_shared(sAlo + row * AS_STRIDE + col);
                ldsm4(al[mt], ad);
            }
            #pragma unroll
            for (int nt2 = 0; nt2 < 2; nt2++) {
                int row = k16 * 16 + (lane & 15);
                int col = wn + nt2 * 16 + ((lane >> 4) & 1) * 8;
                uint32_t t[4];
                uint32_t ad = (uint32_t)__cvta_generic_to_shared(sBhi + row * BS_STRIDE + col);
                ldsm4t(t, ad);
                bh[nt2 * 2][0] = t[0]; bh[nt2 * 2][1] = t[1];
                bh[nt2 * 2 + 1][0] = t[2]; bh[nt2 * 2 + 1][1] = t[3];
                ad = (uint32_t)__cvta_generic_to_shared(sBlo + row * BS_STRIDE + col);
                ldsm4t(t, ad);
                bl[nt2 * 2][0] = t[0]; bl[nt2 * 2][1] = t[1];
                bl[nt2 * 2 + 1][0] = t[2]; bl[nt2 * 2 + 1][1] = t[3];
            }
            #pragma unroll
            for (int mt = 0; mt < 5; mt++)
                #pragma unroll
                for (int nt = 0; nt < 4; nt++) {
                    mma16816(acc[mt][nt], ah[mt], bh[nt]);
                    mma16816(acc[mt][nt], ah[mt], bl[nt]);
                    mma16816(acc[mt][nt], al[mt], bh[nt]);
                }
        }
        __syncthreads();
    }

    if (mode == 0) {
        // epilogue: bias + relu -> fp16
        #pragma unroll
        for (int mt = 0; mt < 5; mt++) {
            int r0 = m0 + wm + mt * 16 + (lane >> 2);
            int r1 = r0 + 8;
            #pragma unroll
            for (int nt = 0; nt < 4; nt++) {
                int cl = wn + nt * 8 + (lane & 3) * 2;
                float b0 = sbias[cl], b1 = sbias[cl + 1];
                float v0 = fmaxf(acc[mt][nt][0] + b0, 0.f);
                float v1 = fmaxf(acc[mt][nt][1] + b1, 0.f);
                float v2 = fmaxf(acc[mt][nt][2] + b0, 0.f);
                float v3 = fmaxf(acc[mt][nt][3] + b1, 0.f);
                if (r0 < NN)
                    *(__half2*)(C16 + (size_t)r0 * 256 + n0 + cl) = __floats2half2_rn(v0, v1);
                if (r1 < NN)
                    *(__half2*)(C16 + (size_t)r1 * 256 + n0 + cl) = __floats2half2_rn(v2, v3);
            }
        }
    } else {
        // fused heads: PI partial = acc . Wp, V partial = acc . Wv (raw, bias handled in init)
        float wp[8], wv[8];
        #pragma unroll
        for (int nt = 0; nt < 4; nt++) {
            int cg = n0 + wn + nt * 8 + (lane & 3) * 2;
            wp[nt * 2] = Wp[cg]; wp[nt * 2 + 1] = Wp[cg + 1];
            wv[nt * 2] = Wv[cg]; wv[nt * 2 + 1] = Wv[cg + 1];
        }
        for (int i = tid; i < MT; i += 256) spi[i] = 0.f;
        __syncthreads();
        float vth = 0.f;
        #pragma unroll
        for (int mt = 0; mt < 5; mt++) {
            float p0 = 0.f, p1 = 0.f, q0 = 0.f, q1 = 0.f;
            #pragma unroll
            for (int nt = 0; nt < 4; nt++) {
                p0 += acc[mt][nt][0] * wp[nt * 2] + acc[mt][nt][1] * wp[nt * 2 + 1];
                p1 += acc[mt][nt][2] * wp[nt * 2] + acc[mt][nt][3] * wp[nt * 2 + 1];
                q0 += acc[mt][nt][0] * wv[nt * 2] + acc[mt][nt][1] * wv[nt * 2 + 1];
                q1 += acc[mt][nt][2] * wv[nt * 2] + acc[mt][nt][3] * wv[nt * 2 + 1];
            }
            #pragma unroll
            for (int o = 1; o <= 2; o <<= 1) {
                p0 += __shfl_xor_sync(0xffffffffu, p0, o);
                p1 += __shfl_xor_sync(0xffffffffu, p1, o);
                q0 += __shfl_xor_sync(0xffffffffu, q0, o);
                q1 += __shfl_xor_sync(0xffffffffu, q1, o);
            }
            if ((lane & 3) == 0) {
                int lr = wm + mt * 16 + (lane >> 2);
                atomicAdd(&spi[lr], p0);
                atomicAdd(&spi[lr + 8], p1);
                vth += q0 + q1;
            }
        }
        // V: warp reduce then block reduce
        #pragma unroll
        for (int o = 16; o > 0; o >>= 1) vth += __shfl_xor_sync(0xffffffffu, vth, o);
        if (lane == 0) svred[wid] = vth;
        __syncthreads();
        for (int i = tid; i < MT; i += 256) {
            int gr = m0 + i;
            if (gr < NN) atomicAdd(&out[gr], spi[i]);
        }
        if (tid == 0) {
            float s = 0.f;
            #pragma unroll
            for (int w = 0; w < 8; w++) s += svred[w];
            atomicAdd(&g_vsum, s);
        }
    }
}

__global__ void final_kernel(const float* __restrict__ bv, float* __restrict__ out) {
    if (threadIdx.x == 0)
        out[NN] = g_vsum * (1.0f / (float)NN) + g_dotv + bv[0];
}

// ---------------- launch ----------------
extern "C" void kernel_launch(void* const* d_in, const int* in_sizes, int n_in,
                              void* d_out, int out_size) {
    const float* features = (const float*)d_in[0];
    const int*   src      = (const int*)d_in[1];
    const int*   dst      = (const int*)d_in[2];
    const float* W1 = (const float*)d_in[3];
    const float* b1 = (const float*)d_in[4];
    const float* W2 = (const float*)d_in[5];
    const float* b2 = (const float*)d_in[6];
    const float* W3 = (const float*)d_in[7];
    const float* b3 = (const float*)d_in[8];
    const float* Wp = (const float*)d_in[9];
    const float* bp = (const float*)d_in[10];
    const float* Wv = (const float*)d_in[11];
    const float* bv = (const float*)d_in[12];
    float* out = (float*)d_out;

    void *pX16_, *pAhi_, *pAlo_, *pWhi_, *pWlo_;
    cudaGetSymbolAddress(&pX16_, g_x16);
    cudaGetSymbolAddress(&pAhi_, g_ahi);
    cudaGetSymbolAddress(&pAlo_, g_alo);
    cudaGetSymbolAddress(&pWhi_, g_whi);
    cudaGetSymbolAddress(&pWlo_, g_wlo);
    __half* x16 = (__half*)pX16_;
    __nv_bfloat16* ahi = (__nv_bfloat16*)pAhi_;
    __nv_bfloat16* alo = (__nv_bfloat16*)pAlo_;
    __nv_bfloat16* whi = (__nv_bfloat16*)pWhi_;
    __nv_bfloat16* wlo = (__nv_bfloat16*)pWlo_;

    // graph preprocessing (order-free CSR)
    zero_kernel<<<(NN + 255) / 256, 256>>>();
    count_kernel<<<(NE + 255) / 256, 256>>>(src, dst);
    alloc_kernel<<<(NN + 255) / 256, 256>>>();
    fill_kernel<<<(NE + 255) / 256, 256>>>(src, dst);

    // head constants + output init + conversions
    dots_kernel<<<1, 256>>>(b3, Wp, Wv);
    init_out<<<(NN + 255) / 256, 256>>>(bp, out);
    int conv_threads = NFP + W1P + 2 * W2P;
    convert_all<<<(conv_threads + 255) / 256, 256>>>(features, W1, W2, W3);

    dim3 ggrid((NN + MT - 1) / MT, 2);  // 63 x 2 = 126 CTAs

    // layer 1 (K=128)
    aggregate_kernel<1><<<1250, 256>>>(x16, ahi, alo, 128);
    gemm_mma<<<ggrid, 256>>>(ahi, alo, whi, wlo, b1, x16, Wp, Wv, out, 128, 0);
    // layer 2 (K=256)
    aggregate_kernel<2><<<1250, 256>>>(x16, ahi, alo, 256);
    gemm_mma<<<ggrid, 256>>>(ahi, alo, whi + 32768, wlo + 32768, b2, x16, Wp, Wv, out, 256, 0);
    // layer 3 (K=256): fused heads epilogue
    aggregate_kernel<2><<<1250, 256>>>(x16, ahi, alo, 256);
    gemm_mma<<<ggrid, 256>>>(ahi, alo, whi + 98304, wlo + 98304, b3, x16, Wp, Wv, out, 256, 1);

    final_kernel<<<1, 32>>>(bv, out);
}

// round 9
// speedup vs baseline: 1.2402x; 1.2402x over previous
#include <cuda_runtime.h>
#include <cuda_fp16.h>
#include <cstdint>

#define NN 10000
#define NE 320000
#define F_HID 256

// ---------------- scratch (device globals; no allocation allowed) ----------------
__device__ int   g_deg[NN];
__device__ int   g_incnt[NN];
__device__ int   g_roff[NN];
__device__ int   g_rend[NN];
__device__ int   g_rank[NE];
__device__ int   g_total;
__device__ float g_inv[NN];
__device__ int2  g_csr[NE];                          // (src, w bits)
__device__ __align__(16) __half g_x16[NN * F_HID];   // layer outputs / gather operand
__device__ __align__(16) __half g_agg16[NN * F_HID]; // agg output = GEMM A operand
__device__ __align__(16) __half g_w16[256 * 256 * 3];// fp16 weights
__device__ float g_vsum;
__device__ float g_dotp;   // b3 . Wp
__device__ float g_dotv;   // b3 . Wv

// ---------------- helpers ----------------
__device__ __forceinline__ void ldsm4(uint32_t* r, uint32_t addr) {
    asm volatile("ldmatrix.sync.aligned.m8n8.x4.shared.b16 {%0,%1,%2,%3}, [%4];"
                 : "=r"(r[0]), "=r"(r[1]), "=r"(r[2]), "=r"(r[3]) : "r"(addr));
}
__device__ __forceinline__ void ldsm4t(uint32_t* r, uint32_t addr) {
    asm volatile("ldmatrix.sync.aligned.m8n8.x4.trans.shared.b16 {%0,%1,%2,%3}, [%4];"
                 : "=r"(r[0]), "=r"(r[1]), "=r"(r[2]), "=r"(r[3]) : "r"(addr));
}
__device__ __forceinline__ void mma16816f(float* c, const uint32_t* a, const uint32_t* b) {
    asm volatile(
        "mma.sync.aligned.m16n8k16.row.col.f32.f16.f16.f32 "
        "{%0,%1,%2,%3}, {%4,%5,%6,%7}, {%8,%9}, {%0,%1,%2,%3};"
        : "+f"(c[0]), "+f"(c[1]), "+f"(c[2]), "+f"(c[3])
        : "r"(a[0]), "r"(a[1]), "r"(a[2]), "r"(a[3]), "r"(b[0]), "r"(b[1]));
}

// ---------------- graph preprocessing (+ folded head dot constants) ----------------
__global__ void zero_kernel(const float* __restrict__ b3, const float* __restrict__ Wp,
                            const float* __restrict__ Wv) {
    int i = blockIdx.x * blockDim.x + threadIdx.x;
    if (i < NN) { g_deg[i] = 0; g_incnt[i] = 0; }
    if (blockIdx.x == 0) {
        // block 0 also computes b3.Wp / b3.Wv (256 threads)
        __shared__ float sp[8], sv[8];
        int t = threadIdx.x;
        float pd = b3[t] * Wp[t];
        float pv = b3[t] * Wv[t];
        #pragma unroll
        for (int o = 16; o > 0; o >>= 1) {
            pd += __shfl_xor_sync(0xffffffffu, pd, o);
            pv += __shfl_xor_sync(0xffffffffu, pv, o);
        }
        if ((t & 31) == 0) { sp[t >> 5] = pd; sv[t >> 5] = pv; }
        __syncthreads();
        if (t == 0) {
            float a = 0.f, b = 0.f;
            #pragma unroll
            for (int w = 0; w < 8; w++) { a += sp[w]; b += sv[w]; }
            g_dotp = a; g_dotv = b;
            g_vsum = 0.0f; g_total = 0;
        }
    }
}

__global__ void count_kernel(const int* __restrict__ src, const int* __restrict__ dst) {
    int e = blockIdx.x * blockDim.x + threadIdx.x;
    if (e < NE) {
        atomicAdd(&g_deg[src[e]], 1);
        g_rank[e] = atomicAdd(&g_incnt[dst[e]], 1);
    }
}

// order-free CSR bucket allocation (+ folded PI output init: out[i] = bp + b3.Wp)
__global__ void alloc_kernel(const float* __restrict__ bp, float* __restrict__ out) {
    int i = blockIdx.x * blockDim.x + threadIdx.x;
    if (i < NN) {
        int c = g_incnt[i];
        int base = atomicAdd(&g_total, c);
        g_roff[i] = base;
        g_rend[i] = base + c;
        int d = g_deg[i];
        g_inv[i] = (d > 0) ? 1.0f / (float)d : 0.0f;
        out[i] = bp[0] + g_dotp;
    }
}

__global__ void fill_kernel(const int* __restrict__ src, const int* __restrict__ dst) {
    int e = blockIdx.x * blockDim.x + threadIdx.x;
    if (e < NE) {
        int d = dst[e];
        int s = src[e];
        int p = g_roff[d] + g_rank[e];
        g_csr[p] = make_int2(s, __float_as_int(g_inv[s]));
    }
}

// ---------------- fused conversions: features + W1/W2/W3 -> fp16 ----------------
#define NFP (NN * 128 / 2)
#define W1P (128 * 256 / 2)
#define W2P (256 * 256 / 2)
__global__ void convert_all(const float* __restrict__ X, const float* __restrict__ W1,
                            const float* __restrict__ W2, const float* __restrict__ W3) {
    int t = blockIdx.x * blockDim.x + threadIdx.x;
    if (t < NFP) {
        float2 v = *(const float2*)(X + 2 * t);
        __half2 h = __floats2half2_rn(v.x, v.y);
        *(uint32_t*)((char*)g_x16 + 4 * t) = *reinterpret_cast<uint32_t*>(&h);
        return;
    }
    int u = t - NFP;
    const float* Wsrc;
    int off;
    if (u < W1P) { Wsrc = W1; off = 0; }
    else if (u < W1P + W2P) { Wsrc = W2; off = 32768; u -= W1P; }
    else if (u < W1P + 2 * W2P) { Wsrc = W3; off = 98304; u -= W1P + W2P; }
    else return;
    float2 v = *(const float2*)(Wsrc + 2 * u);
    __half2 h = __floats2half2_rn(v.x, v.y);
    *(uint32_t*)((char*)g_w16 + 2 * (off + 2 * u)) = *reinterpret_cast<uint32_t*>(&h);
}

// ---------------- edge aggregation (fp16 gather, fp32 accum, MLP=4) -> fp16 ----------------
template <int CHUNKS>  // 1: F=128, 2: F=256
__global__ void aggregate_kernel(const __half* __restrict__ X,
                                 __half* __restrict__ Y, int F) {
    int gw    = (blockIdx.x * blockDim.x + threadIdx.x) >> 5;
    int lane  = threadIdx.x & 31;
    int nwrp  = (gridDim.x * blockDim.x) >> 5;
    for (int n = gw; n < NN; n += nwrp) {
        int s0 = g_roff[n], s1 = g_rend[n];
        float4 acc0 = make_float4(0.f, 0.f, 0.f, 0.f);
        float4 acc1 = make_float4(0.f, 0.f, 0.f, 0.f);
        for (int e0 = s0; e0 < s1; e0 += 32) {
            int   ss = 0; float ww = 0.f;
            if (e0 + lane < s1) {
                int2 ev = g_csr[e0 + lane];
                ss = ev.x; ww = __int_as_float(ev.y);
            }
            int cnt = min(32, s1 - e0);
            int j = 0;
            for (; j + 4 <= cnt; j += 4) {
                int sj0 = __shfl_sync(0xffffffffu, ss, j);
                int sj1 = __shfl_sync(0xffffffffu, ss, j + 1);
                int sj2 = __shfl_sync(0xffffffffu, ss, j + 2);
                int sj3 = __shfl_sync(0xffffffffu, ss, j + 3);
                float w0 = __shfl_sync(0xffffffffu, ww, j);
                float w1 = __shfl_sync(0xffffffffu, ww, j + 1);
                float w2 = __shfl_sync(0xffffffffu, ww, j + 2);
                float w3 = __shfl_sync(0xffffffffu, ww, j + 3);
                if (CHUNKS == 1) {
                    uint2 v0 = ((const uint2*)(X + (size_t)sj0 * F))[lane];
                    uint2 v1 = ((const uint2*)(X + (size_t)sj1 * F))[lane];
                    uint2 v2 = ((const uint2*)(X + (size_t)sj2 * F))[lane];
                    uint2 v3 = ((const uint2*)(X + (size_t)sj3 * F))[lane];
                    #define ACC2(vv, wj) { \
                        float2 f0 = __half22float2(*reinterpret_cast<__half2*>(&(vv).x)); \
                        float2 f1 = __half22float2(*reinterpret_cast<__half2*>(&(vv).y)); \
                        acc0.x += (wj) * f0.x; acc0.y += (wj) * f0.y; \
                        acc0.z += (wj) * f1.x; acc0.w += (wj) * f1.y; }
                    ACC2(v0, w0) ACC2(v1, w1) ACC2(v2, w2) ACC2(v3, w3)
                    #undef ACC2
                } else {
                    uint4 v0 = ((const uint4*)(X + (size_t)sj0 * F))[lane];
                    uint4 v1 = ((const uint4*)(X + (size_t)sj1 * F))[lane];
                    uint4 v2 = ((const uint4*)(X + (size_t)sj2 * F))[lane];
                    uint4 v3 = ((const uint4*)(X + (size_t)sj3 * F))[lane];
                    #define ACC4(vv, wj) { \
                        float2 f0 = __half22float2(*reinterpret_cast<__half2*>(&(vv).x)); \
                        float2 f1 = __half22float2(*reinterpret_cast<__half2*>(&(vv).y)); \
                        float2 f2 = __half22float2(*reinterpret_cast<__half2*>(&(vv).z)); \
                        float2 f3 = __half22float2(*reinterpret_cast<__half2*>(&(vv).w)); \
                        acc0.x += (wj) * f0.x; acc0.y += (wj) * f0.y; \
                        acc0.z += (wj) * f1.x; acc0.w += (wj) * f1.y; \
                        acc1.x += (wj) * f2.x; acc1.y += (wj) * f2.y; \
                        acc1.z += (wj) * f3.x; acc1.w += (wj) * f3.y; }
                    ACC4(v0, w0) ACC4(v1, w1) ACC4(v2, w2) ACC4(v3, w3)
                    #undef ACC4
                }
            }
            for (; j < cnt; j++) {
                int   sj = __shfl_sync(0xffffffffu, ss, j);
                float wj = __shfl_sync(0xffffffffu, ww, j);
                if (CHUNKS == 1) {
                    uint2 v = ((const uint2*)(X + (size_t)sj * F))[lane];
                    float2 f0 = __half22float2(*reinterpret_cast<__half2*>(&v.x));
                    float2 f1 = __half22float2(*reinterpret_cast<__half2*>(&v.y));
                    acc0.x += wj * f0.x; acc0.y += wj * f0.y;
                    acc0.z += wj * f1.x; acc0.w += wj * f1.y;
                } else {
                    uint4 v = ((const uint4*)(X + (size_t)sj * F))[lane];
                    float2 f0 = __half22float2(*reinterpret_cast<__half2*>(&v.x));
                    float2 f1 = __half22float2(*reinterpret_cast<__half2*>(&v.y));
                    float2 f2 = __half22float2(*reinterpret_cast<__half2*>(&v.z));
                    float2 f3 = __half22float2(*reinterpret_cast<__half2*>(&v.w));
                    acc0.x += wj * f0.x; acc0.y += wj * f0.y;
                    acc0.z += wj * f1.x; acc0.w += wj * f1.y;
                    acc1.x += wj * f2.x; acc1.y += wj * f2.y;
                    acc1.z += wj * f3.x; acc1.w += wj * f3.y;
                }
            }
        }
        __half2 p0 = __floats2half2_rn(acc0.x, acc0.y);
        __half2 p1 = __floats2half2_rn(acc0.z, acc0.w);
        if (CHUNKS == 1) {
            ((uint2*)(Y + (size_t)n * F))[lane] =
                make_uint2(*reinterpret_cast<uint32_t*>(&p0), *reinterpret_cast<uint32_t*>(&p1));
        } else {
            __half2 p2 = __floats2half2_rn(acc1.x, acc1.y);
            __half2 p3 = __floats2half2_rn(acc1.z, acc1.w);
            ((uint4*)(Y + (size_t)n * F))[lane] =
                make_uint4(*reinterpret_cast<uint32_t*>(&p0), *reinterpret_cast<uint32_t*>(&p1),
                           *reinterpret_cast<uint32_t*>(&p2), *reinterpret_cast<uint32_t*>(&p3));
        }
    }
}

// ---------------- GEMM via mma.sync fp16 (single product) ----------------
// CTA tile 160x128, 8 warps (2m x 4n), warp tile 80x32, BK=32 -> 126 CTAs (single wave)
// mode 0: relu + fp16 out (C16)
// mode 1: fused heads epilogue
#define MT 160
#define AS_STRIDE 40
#define BS_STRIDE 136
__global__ void __launch_bounds__(256)
gemm_mma(const __half* __restrict__ A, const __half* __restrict__ W16,
         const float* __restrict__ bias, __half* __restrict__ C16,
         const float* __restrict__ Wp, const float* __restrict__ Wv,
         float* __restrict__ out, int K, int mode) {
    __shared__ __align__(16) __half sA[MT * AS_STRIDE];
    __shared__ __align__(16) __half sB[32 * BS_STRIDE];
    __shared__ float sbias[128];
    __shared__ float spi[MT];
    __shared__ float svred[8];

    int tid = threadIdx.x;
    int m0 = blockIdx.x * MT, n0 = blockIdx.y * 128;
    if (tid < 128) sbias[tid] = bias[n0 + tid];
    int wid = tid >> 5, lane = tid & 31;
    int wm = (wid & 1) * 80, wn = (wid >> 1) * 32;

    float acc[5][4][4];
    #pragma unroll
    for (int i = 0; i < 5; i++)
        #pragma unroll
        for (int j = 0; j < 4; j++)
            #pragma unroll
            for (int q = 0; q < 4; q++) acc[i][j][q] = 0.f;

    const uint4 z4 = make_uint4(0, 0, 0, 0);

    for (int kc = 0; kc < K; kc += 32) {
        // stage A: MT rows x 32 k
        #pragma unroll
        for (int idx = tid; idx < MT * 4; idx += 256) {
            int row = idx >> 2, c16 = idx & 3;
            int gr = m0 + row;
            uint4 vh = z4;
            if (gr < NN)
                vh = *(const uint4*)(A + (size_t)gr * K + kc + c16 * 8);
            *(uint4*)(sA + row * AS_STRIDE + c16 * 8) = vh;
        }
        // stage B: 32 k rows x 128 n
        #pragma unroll
        for (int idx = tid; idx < 512; idx += 256) {
            int row = idx >> 4, c16 = idx & 15;
            *(uint4*)(sB + row * BS_STRIDE + c16 * 8) =
                *(const uint4*)(W16 + (size_t)(kc + row) * 256 + n0 + c16 * 8);
        }
        __syncthreads();

        #pragma unroll
        for (int k16 = 0; k16 < 2; k16++) {
            uint32_t ah[5][4], bh[4][2];
            #pragma unroll
            for (int mt = 0; mt < 5; mt++) {
                int row = wm + mt * 16 + (lane & 15);
                int col = k16 * 16 + (lane >> 4) * 8;
                uint32_t ad = (uint32_t)__cvta_generic_to_shared(sA + row * AS_STRIDE + col);
                ldsm4(ah[mt], ad);
            }
            #pragma unroll
            for (int nt2 = 0; nt2 < 2; nt2++) {
                int row = k16 * 16 + (lane & 15);
                int col = wn + nt2 * 16 + ((lane >> 4) & 1) * 8;
                uint32_t t[4];
                uint32_t ad = (uint32_t)__cvta_generic_to_shared(sB + row * BS_STRIDE + col);
                ldsm4t(t, ad);
                bh[nt2 * 2][0] = t[0]; bh[nt2 * 2][1] = t[1];
                bh[nt2 * 2 + 1][0] = t[2]; bh[nt2 * 2 + 1][1] = t[3];
            }
            #pragma unroll
            for (int mt = 0; mt < 5; mt++)
                #pragma unroll
                for (int nt = 0; nt < 4; nt++)
                    mma16816f(acc[mt][nt], ah[mt], bh[nt]);
        }
        __syncthreads();
    }

    if (mode == 0) {
        #pragma unroll
        for (int mt = 0; mt < 5; mt++) {
            int r0 = m0 + wm + mt * 16 + (lane >> 2);
            int r1 = r0 + 8;
            #pragma unroll
            for (int nt = 0; nt < 4; nt++) {
                int cl = wn + nt * 8 + (lane & 3) * 2;
                float b0 = sbias[cl], b1 = sbias[cl + 1];
                float v0 = fmaxf(acc[mt][nt][0] + b0, 0.f);
                float v1 = fmaxf(acc[mt][nt][1] + b1, 0.f);
                float v2 = fmaxf(acc[mt][nt][2] + b0, 0.f);
                float v3 = fmaxf(acc[mt][nt][3] + b1, 0.f);
                if (r0 < NN)
                    *(__half2*)(C16 + (size_t)r0 * 256 + n0 + cl) = __floats2half2_rn(v0, v1);
                if (r1 < NN)
                    *(__half2*)(C16 + (size_t)r1 * 256 + n0 + cl) = __floats2half2_rn(v2, v3);
            }
        }
    } else {
        // fused heads: PI partials into out, V partials into g_vsum
        float wp[8], wv[8];
        #pragma unroll
        for (int nt = 0; nt < 4; nt++) {
            int cg = n0 + wn + nt * 8 + (lane & 3) * 2;
            wp[nt * 2] = Wp[cg]; wp[nt * 2 + 1] = Wp[cg + 1];
            wv[nt * 2] = Wv[cg]; wv[nt * 2 + 1] = Wv[cg + 1];
        }
        for (int i = tid; i < MT; i += 256) spi[i] = 0.f;
        __syncthreads();
        float vth = 0.f;
        #pragma unroll
        for (int mt = 0; mt < 5; mt++) {
            float p0 = 0.f, p1 = 0.f, q0 = 0.f, q1 = 0.f;
            #pragma unroll
            for (int nt = 0; nt < 4; nt++) {
                p0 += acc[mt][nt][0] * wp[nt * 2] + acc[mt][nt][1] * wp[nt * 2 + 1];
                p1 += acc[mt][nt][2] * wp[nt * 2] + acc[mt][nt][3] * wp[nt * 2 + 1];
                q0 += acc[mt][nt][0] * wv[nt * 2] + acc[mt][nt][1] * wv[nt * 2 + 1];
                q1 += acc[mt][nt][2] * wv[nt * 2] + acc[mt][nt][3] * wv[nt * 2 + 1];
            }
            #pragma unroll
            for (int o = 1; o <= 2; o <<= 1) {
                p0 += __shfl_xor_sync(0xffffffffu, p0, o);
                p1 += __shfl_xor_sync(0xffffffffu, p1, o);
                q0 += __shfl_xor_sync(0xffffffffu, q0, o);
                q1 += __shfl_xor_sync(0xffffffffu, q1, o);
            }
            if ((lane & 3) == 0) {
                int lr = wm + mt * 16 + (lane >> 2);
                atomicAdd(&spi[lr], p0);
                atomicAdd(&spi[lr + 8], p1);
                vth += q0 + q1;
            }
        }
        #pragma unroll
        for (int o = 16; o > 0; o >>= 1) vth += __shfl_xor_sync(0xffffffffu, vth, o);
        if (lane == 0) svred[wid] = vth;
        __syncthreads();
        for (int i = tid; i < MT; i += 256) {
            int gr = m0 + i;
            if (gr < NN) atomicAdd(&out[gr], spi[i]);
        }
        if (tid == 0) {
            float s = 0.f;
            #pragma unroll
            for (int w = 0; w < 8; w++) s += svred[w];
            atomicAdd(&g_vsum, s);
        }
    }
}

__global__ void final_kernel(const float* __restrict__ bv, float* __restrict__ out) {
    if (threadIdx.x == 0)
        out[NN] = g_vsum * (1.0f / (float)NN) + g_dotv + bv[0];
}

// ---------------- launch ----------------
extern "C" void kernel_launch(void* const* d_in, const int* in_sizes, int n_in,
                              void* d_out, int out_size) {
    const float* features = (const float*)d_in[0];
    const int*   src      = (const int*)d_in[1];
    const int*   dst      = (const int*)d_in[2];
    const float* W1 = (const float*)d_in[3];
    const float* b1 = (const float*)d_in[4];
    const float* W2 = (const float*)d_in[5];
    const float* b2 = (const float*)d_in[6];
    const float* W3 = (const float*)d_in[7];
    const float* b3 = (const float*)d_in[8];
    const float* Wp = (const float*)d_in[9];
    const float* bp = (const float*)d_in[10];
    const float* Wv = (const float*)d_in[11];
    const float* bv = (const float*)d_in[12];
    float* out = (float*)d_out;

    void *pX16_, *pAgg_, *pW16_;
    cudaGetSymbolAddress(&pX16_, g_x16);
    cudaGetSymbolAddress(&pAgg_, g_agg16);
    cudaGetSymbolAddress(&pW16_, g_w16);
    __half* x16 = (__half*)pX16_;
    __half* agg16 = (__half*)pAgg_;
    __half* w16 = (__half*)pW16_;

    // graph preprocessing (order-free CSR; head constants folded in)
    zero_kernel<<<(NN + 255) / 256, 256>>>(b3, Wp, Wv);
    count_kernel<<<(NE + 255) / 256, 256>>>(src, dst);
    alloc_kernel<<<(NN + 255) / 256, 256>>>(bp, out);
    fill_kernel<<<(NE + 255) / 256, 256>>>(src, dst);

    // conversions (features + all weights -> fp16)
    int conv_threads = NFP + W1P + 2 * W2P;
    convert_all<<<(conv_threads + 255) / 256, 256>>>(features, W1, W2, W3);

    dim3 ggrid((NN + MT - 1) / MT, 2);  // 63 x 2 = 126 CTAs

    // layer 1 (K=128)
    aggregate_kernel<1><<<1250, 256>>>(x16, agg16, 128);
    gemm_mma<<<ggrid, 256>>>(agg16, w16, b1, x16, Wp, Wv, out, 128, 0);
    // layer 2 (K=256)
    aggregate_kernel<2><<<1250, 256>>>(x16, agg16, 256);
    gemm_mma<<<ggrid, 256>>>(agg16, w16 + 32768, b2, x16, Wp, Wv, out, 256, 0);
    // layer 3 (K=256): fused heads epilogue
    aggregate_kernel<2><<<1250, 256>>>(x16, agg16, 256);
    gemm_mma<<<ggrid, 256>>>(agg16, w16 + 98304, b3, x16, Wp, Wv, out, 256, 1);

    final_kernel<<<1, 32>>>(bv, out);
}

// round 10
// speedup vs baseline: 1.2778x; 1.0303x over previous
#include <cuda_runtime.h>
#include <cuda_fp16.h>
#include <cstdint>

#define NN 10000
#define NE 320000
#define F_HID 256

// ---------------- scratch (device globals; no allocation allowed) ----------------
__device__ int   g_deg[NN];
__device__ int   g_incnt[NN];
__device__ int   g_roff[NN];
__device__ int   g_rend[NN];
__device__ int   g_rank[NE];
__device__ int   g_total;
__device__ float g_inv[NN];
__device__ int2  g_csr[NE];                          // (src, w bits)
__device__ __align__(16) __half g_x16[NN * F_HID];   // layer outputs / gather operand
__device__ __align__(16) __half g_agg16[NN * F_HID]; // agg output = GEMM A operand
__device__ __align__(16) __half g_w16[256 * 256 * 3];// fp16 weights
__device__ float g_vsum;
__device__ float g_dotp;   // b3 . Wp
__device__ float g_dotv;   // b3 . Wv

// ---------------- helpers ----------------
__device__ __forceinline__ void ldsm4(uint32_t* r, uint32_t addr) {
    asm volatile("ldmatrix.sync.aligned.m8n8.x4.shared.b16 {%0,%1,%2,%3}, [%4];"
                 : "=r"(r[0]), "=r"(r[1]), "=r"(r[2]), "=r"(r[3]) : "r"(addr));
}
__device__ __forceinline__ void ldsm4t(uint32_t* r, uint32_t addr) {
    asm volatile("ldmatrix.sync.aligned.m8n8.x4.trans.shared.b16 {%0,%1,%2,%3}, [%4];"
                 : "=r"(r[0]), "=r"(r[1]), "=r"(r[2]), "=r"(r[3]) : "r"(addr));
}
__device__ __forceinline__ void mma16816f(float* c, const uint32_t* a, const uint32_t* b) {
    asm volatile(
        "mma.sync.aligned.m16n8k16.row.col.f32.f16.f16.f32 "
        "{%0,%1,%2,%3}, {%4,%5,%6,%7}, {%8,%9}, {%0,%1,%2,%3};"
        : "+f"(c[0]), "+f"(c[1]), "+f"(c[2]), "+f"(c[3])
        : "r"(a[0]), "r"(a[1]), "r"(a[2]), "r"(a[3]), "r"(b[0]), "r"(b[1]));
}

// ---------------- graph preprocessing (+ folded head dot constants) ----------------
__global__ void zero_kernel(const float* __restrict__ b3, const float* __restrict__ Wp,
                            const float* __restrict__ Wv) {
    int i = blockIdx.x * blockDim.x + threadIdx.x;
    if (i < NN) { g_deg[i] = 0; g_incnt[i] = 0; }
    if (blockIdx.x == 0) {
        __shared__ float sp[8], sv[8];
        int t = threadIdx.x;
        float pd = b3[t] * Wp[t];
        float pv = b3[t] * Wv[t];
        #pragma unroll
        for (int o = 16; o > 0; o >>= 1) {
            pd += __shfl_xor_sync(0xffffffffu, pd, o);
            pv += __shfl_xor_sync(0xffffffffu, pv, o);
        }
        if ((t & 31) == 0) { sp[t >> 5] = pd; sv[t >> 5] = pv; }
        __syncthreads();
        if (t == 0) {
            float a = 0.f, b = 0.f;
            #pragma unroll
            for (int w = 0; w < 8; w++) { a += sp[w]; b += sv[w]; }
            g_dotp = a; g_dotv = b;
            g_vsum = 0.0f; g_total = 0;
        }
    }
}

// ---------------- count + fused conversions (independent work, one launch) ----------------
#define NFP (NN * 128 / 2)          // 640000
#define W1P (128 * 256 / 2)         // 16384
#define W2P (256 * 256 / 2)         // 32768
#define CONV_TOTAL (NFP + W1P + 2 * W2P)  // 721920
__global__ void count_conv_kernel(const int* __restrict__ src, const int* __restrict__ dst,
                                  const float* __restrict__ X, const float* __restrict__ W1,
                                  const float* __restrict__ W2, const float* __restrict__ W3) {
    int t = blockIdx.x * blockDim.x + threadIdx.x;
    if (t < NE) {
        atomicAdd(&g_deg[src[t]], 1);
        g_rank[t] = atomicAdd(&g_incnt[dst[t]], 1);
    }
    if (t < CONV_TOTAL) {
        if (t < NFP) {
            float2 v = *(const float2*)(X + 2 * t);
            __half2 h = __floats2half2_rn(v.x, v.y);
            *(uint32_t*)((char*)g_x16 + 4 * t) = *reinterpret_cast<uint32_t*>(&h);
        } else {
            int u = t - NFP;
            const float* Wsrc;
            int off;
            if (u < W1P) { Wsrc = W1; off = 0; }
            else if (u < W1P + W2P) { Wsrc = W2; off = 32768; u -= W1P; }
            else { Wsrc = W3; off = 98304; u -= W1P + W2P; }
            float2 v = *(const float2*)(Wsrc + 2 * u);
            __half2 h = __floats2half2_rn(v.x, v.y);
            *(uint32_t*)((char*)g_w16 + 2 * (off + 2 * u)) = *reinterpret_cast<uint32_t*>(&h);
        }
    }
}

// order-free CSR bucket allocation (+ folded PI output init)
__global__ void alloc_kernel(const float* __restrict__ bp, float* __restrict__ out) {
    int i = blockIdx.x * blockDim.x + threadIdx.x;
    if (i < NN) {
        int c = g_incnt[i];
        int base = atomicAdd(&g_total, c);
        g_roff[i] = base;
        g_rend[i] = base + c;
        int d = g_deg[i];
        g_inv[i] = (d > 0) ? 1.0f / (float)d : 0.0f;
        out[i] = bp[0] + g_dotp;
    }
}

__global__ void fill_kernel(const int* __restrict__ src, const int* __restrict__ dst) {
    int e = blockIdx.x * blockDim.x + threadIdx.x;
    if (e < NE) {
        int d = dst[e];
        int s = src[e];
        int p = g_roff[d] + g_rank[e];
        g_csr[p] = make_int2(s, __float_as_int(g_inv[s]));
    }
}

// ---------------- edge aggregation (fp16 gather, fp32 accum, MLP=8) -> fp16 ----------------
template <int CHUNKS>  // 1: F=128, 2: F=256
__global__ void aggregate_kernel(const __half* __restrict__ X,
                                 __half* __restrict__ Y, int F) {
    int gw    = (blockIdx.x * blockDim.x + threadIdx.x) >> 5;
    int lane  = threadIdx.x & 31;
    int nwrp  = (gridDim.x * blockDim.x) >> 5;
    for (int n = gw; n < NN; n += nwrp) {
        int s0 = g_roff[n], s1 = g_rend[n];
        float4 acc0 = make_float4(0.f, 0.f, 0.f, 0.f);
        float4 acc1 = make_float4(0.f, 0.f, 0.f, 0.f);
        for (int e0 = s0; e0 < s1; e0 += 32) {
            int   ss = 0; float ww = 0.f;
            if (e0 + lane < s1) {
                int2 ev = g_csr[e0 + lane];
                ss = ev.x; ww = __int_as_float(ev.y);
            }
            int cnt = min(32, s1 - e0);
            int j = 0;
            // 8-way unrolled: 8 independent gathers in flight
            for (; j + 8 <= cnt; j += 8) {
                int   sj[8];
                float wj[8];
                #pragma unroll
                for (int q = 0; q < 8; q++) {
                    sj[q] = __shfl_sync(0xffffffffu, ss, j + q);
                    wj[q] = __shfl_sync(0xffffffffu, ww, j + q);
                }
                if (CHUNKS == 1) {
                    uint2 v[8];
                    #pragma unroll
                    for (int q = 0; q < 8; q++)
                        v[q] = ((const uint2*)(X + (size_t)sj[q] * F))[lane];
                    #pragma unroll
                    for (int q = 0; q < 8; q++) {
                        float2 f0 = __half22float2(*reinterpret_cast<__half2*>(&v[q].x));
                        float2 f1 = __half22float2(*reinterpret_cast<__half2*>(&v[q].y));
                        acc0.x += wj[q] * f0.x; acc0.y += wj[q] * f0.y;
                        acc0.z += wj[q] * f1.x; acc0.w += wj[q] * f1.y;
                    }
                } else {
                    uint4 v[8];
                    #pragma unroll
                    for (int q = 0; q < 8; q++)
                        v[q] = ((const uint4*)(X + (size_t)sj[q] * F))[lane];
                    #pragma unroll
                    for (int q = 0; q < 8; q++) {
                        float2 f0 = __half22float2(*reinterpret_cast<__half2*>(&v[q].x));
                        float2 f1 = __half22float2(*reinterpret_cast<__half2*>(&v[q].y));
                        float2 f2 = __half22float2(*reinterpret_cast<__half2*>(&v[q].z));
                        float2 f3 = __half22float2(*reinterpret_cast<__half2*>(&v[q].w));
                        acc0.x += wj[q] * f0.x; acc0.y += wj[q] * f0.y;
                        acc0.z += wj[q] * f1.x; acc0.w += wj[q] * f1.y;
                        acc1.x += wj[q] * f2.x; acc1.y += wj[q] * f2.y;
                        acc1.z += wj[q] * f3.x; acc1.w += wj[q] * f3.y;
                    }
                }
            }
            for (; j < cnt; j++) {
                int   sj = __shfl_sync(0xffffffffu, ss, j);
                float wj = __shfl_sync(0xffffffffu, ww, j);
                if (CHUNKS == 1) {
                    uint2 v = ((const uint2*)(X + (size_t)sj * F))[lane];
                    float2 f0 = __half22float2(*reinterpret_cast<__half2*>(&v.x));
                    float2 f1 = __half22float2(*reinterpret_cast<__half2*>(&v.y));
                    acc0.x += wj * f0.x; acc0.y += wj * f0.y;
                    acc0.z += wj * f1.x; acc0.w += wj * f1.y;
                } else {
                    uint4 v = ((const uint4*)(X + (size_t)sj * F))[lane];
                    float2 f0 = __half22float2(*reinterpret_cast<__half2*>(&v.x));
                    float2 f1 = __half22float2(*reinterpret_cast<__half2*>(&v.y));
                    float2 f2 = __half22float2(*reinterpret_cast<__half2*>(&v.z));
                    float2 f3 = __half22float2(*reinterpret_cast<__half2*>(&v.w));
                    acc0.x += wj * f0.x; acc0.y += wj * f0.y;
                    acc0.z += wj * f1.x; acc0.w += wj * f1.y;
                    acc1.x += wj * f2.x; acc1.y += wj * f2.y;
                    acc1.z += wj * f3.x; acc1.w += wj * f3.y;
                }
            }
        }
        __half2 p0 = __floats2half2_rn(acc0.x, acc0.y);
        __half2 p1 = __floats2half2_rn(acc0.z, acc0.w);
        if (CHUNKS == 1) {
            ((uint2*)(Y + (size_t)n * F))[lane] =
                make_uint2(*reinterpret_cast<uint32_t*>(&p0), *reinterpret_cast<uint32_t*>(&p1));
        } else {
            __half2 p2 = __floats2half2_rn(acc1.x, acc1.y);
            __half2 p3 = __floats2half2_rn(acc1.z, acc1.w);
            ((uint4*)(Y + (size_t)n * F))[lane] =
                make_uint4(*reinterpret_cast<uint32_t*>(&p0), *reinterpret_cast<uint32_t*>(&p1),
                           *reinterpret_cast<uint32_t*>(&p2), *reinterpret_cast<uint32_t*>(&p3));
        }
    }
}

// ---------------- GEMM via mma.sync fp16 (single product) ----------------
// CTA tile 160x128, 8 warps (2m x 4n), warp tile 80x32, BK=32 -> 126 CTAs (single wave)
#define MT 160
#define AS_STRIDE 40
#define BS_STRIDE 136
__global__ void __launch_bounds__(256)
gemm_mma(const __half* __restrict__ A, const __half* __restrict__ W16,
         const float* __restrict__ bias, __half* __restrict__ C16,
         const float* __restrict__ Wp, const float* __restrict__ Wv,
         float* __restrict__ out, int K, int mode) {
    __shared__ __align__(16) __half sA[MT * AS_STRIDE];
    __shared__ __align__(16) __half sB[32 * BS_STRIDE];
    __shared__ float sbias[128];
    __shared__ float spi[MT];
    __shared__ float svred[8];

    int tid = threadIdx.x;
    int m0 = blockIdx.x * MT, n0 = blockIdx.y * 128;
    if (tid < 128) sbias[tid] = bias[n0 + tid];
    int wid = tid >> 5, lane = tid & 31;
    int wm = (wid & 1) * 80, wn = (wid >> 1) * 32;

    float acc[5][4][4];
    #pragma unroll
    for (int i = 0; i < 5; i++)
        #pragma unroll
        for (int j = 0; j < 4; j++)
            #pragma unroll
            for (int q = 0; q < 4; q++) acc[i][j][q] = 0.f;

    const uint4 z4 = make_uint4(0, 0, 0, 0);

    for (int kc = 0; kc < K; kc += 32) {
        #pragma unroll
        for (int idx = tid; idx < MT * 4; idx += 256) {
            int row = idx >> 2, c16 = idx & 3;
            int gr = m0 + row;
            uint4 vh = z4;
            if (gr < NN)
                vh = *(const uint4*)(A + (size_t)gr * K + kc + c16 * 8);
            *(uint4*)(sA + row * AS_STRIDE + c16 * 8) = vh;
        }
        #pragma unroll
        for (int idx = tid; idx < 512; idx += 256) {
            int row = idx >> 4, c16 = idx & 15;
            *(uint4*)(sB + row * BS_STRIDE + c16 * 8) =
                *(const uint4*)(W16 + (size_t)(kc + row) * 256 + n0 + c16 * 8);
        }
        __syncthreads();

        #pragma unroll
        for (int k16 = 0; k16 < 2; k16++) {
            uint32_t ah[5][4], bh[4][2];
            #pragma unroll
            for (int mt = 0; mt < 5; mt++) {
                int row = wm + mt * 16 + (lane & 15);
                int col = k16 * 16 + (lane >> 4) * 8;
                uint32_t ad = (uint32_t)__cvta_generic_to_shared(sA + row * AS_STRIDE + col);
                ldsm4(ah[mt], ad);
            }
            #pragma unroll
            for (int nt2 = 0; nt2 < 2; nt2++) {
                int row = k16 * 16 + (lane & 15);
                int col = wn + nt2 * 16 + ((lane >> 4) & 1) * 8;
                uint32_t t[4];
                uint32_t ad = (uint32_t)__cvta_generic_to_shared(sB + row * BS_STRIDE + col);
                ldsm4t(t, ad);
                bh[nt2 * 2][0] = t[0]; bh[nt2 * 2][1] = t[1];
                bh[nt2 * 2 + 1][0] = t[2]; bh[nt2 * 2 + 1][1] = t[3];
            }
            #pragma unroll
            for (int mt = 0; mt < 5; mt++)
                #pragma unroll
                for (int nt = 0; nt < 4; nt++)
                    mma16816f(acc[mt][nt], ah[mt], bh[nt]);
        }
        __syncthreads();
    }

    if (mode == 0) {
        #pragma unroll
        for (int mt = 0; mt < 5; mt++) {
            int r0 = m0 + wm + mt * 16 + (lane >> 2);
            int r1 = r0 + 8;
            #pragma unroll
            for (int nt = 0; nt < 4; nt++) {
                int cl = wn + nt * 8 + (lane & 3) * 2;
                float b0 = sbias[cl], b1 = sbias[cl + 1];
                float v0 = fmaxf(acc[mt][nt][0] + b0, 0.f);
                float v1 = fmaxf(acc[mt][nt][1] + b1, 0.f);
                float v2 = fmaxf(acc[mt][nt][2] + b0, 0.f);
                float v3 = fmaxf(acc[mt][nt][3] + b1, 0.f);
                if (r0 < NN)
                    *(__half2*)(C16 + (size_t)r0 * 256 + n0 + cl) = __floats2half2_rn(v0, v1);
                if (r1 < NN)
                    *(__half2*)(C16 + (size_t)r1 * 256 + n0 + cl) = __floats2half2_rn(v2, v3);
            }
        }
    } else {
        float wp[8], wv[8];
        #pragma unroll
        for (int nt = 0; nt < 4; nt++) {
            int cg = n0 + wn + nt * 8 + (lane & 3) * 2;
            wp[nt * 2] = Wp[cg]; wp[nt * 2 + 1] = Wp[cg + 1];
            wv[nt * 2] = Wv[cg]; wv[nt * 2 + 1] = Wv[cg + 1];
        }
        for (int i = tid; i < MT; i += 256) spi[i] = 0.f;
        __syncthreads();
        float vth = 0.f;
        #pragma unroll
        for (int mt = 0; mt < 5; mt++) {
            float p0 = 0.f, p1 = 0.f, q0 = 0.f, q1 = 0.f;
            #pragma unroll
            for (int nt = 0; nt < 4; nt++) {
                p0 += acc[mt][nt][0] * wp[nt * 2] + acc[mt][nt][1] * wp[nt * 2 + 1];
                p1 += acc[mt][nt][2] * wp[nt * 2] + acc[mt][nt][3] * wp[nt * 2 + 1];
                q0 += acc[mt][nt][0] * wv[nt * 2] + acc[mt][nt][1] * wv[nt * 2 + 1];
                q1 += acc[mt][nt][2] * wv[nt * 2] + acc[mt][nt][3] * wv[nt * 2 + 1];
            }
            #pragma unroll
            for (int o = 1; o <= 2; o <<= 1) {
                p0 += __shfl_xor_sync(0xffffffffu, p0, o);
                p1 += __shfl_xor_sync(0xffffffffu, p1, o);
                q0 += __shfl_xor_sync(0xffffffffu, q0, o);
                q1 += __shfl_xor_sync(0xffffffffu, q1, o);
            }
            if ((lane & 3) == 0) {
                int lr = wm + mt * 16 + (lane >> 2);
                atomicAdd(&spi[lr], p0);
                atomicAdd(&spi[lr + 8], p1);
                vth += q0 + q1;
            }
        }
        #pragma unroll
        for (int o = 16; o > 0; o >>= 1) vth += __shfl_xor_sync(0xffffffffu, vth, o);
        if (lane == 0) svred[wid] = vth;
        __syncthreads();
        for (int i = tid; i < MT; i += 256) {
            int gr = m0 + i;
            if (gr < NN) atomicAdd(&out[gr], spi[i]);
        }
        if (tid == 0) {
            float s = 0.f;
            #pragma unroll
            for (int w = 0; w < 8; w++) s += svred[w];
            atomicAdd(&g_vsum, s);
        }
    }
}

__global__ void final_kernel(const float* __restrict__ bv, float* __restrict__ out) {
    if (threadIdx.x == 0)
        out[NN] = g_vsum * (1.0f / (float)NN) + g_dotv + bv[0];
}

// ---------------- launch ----------------
extern "C" void kernel_launch(void* const* d_in, const int* in_sizes, int n_in,
                              void* d_out, int out_size) {
    const float* features = (const float*)d_in[0];
    const int*   src      = (const int*)d_in[1];
    const int*   dst      = (const int*)d_in[2];
    const float* W1 = (const float*)d_in[3];
    const float* b1 = (const float*)d_in[4];
    const float* W2 = (const float*)d_in[5];
    const float* b2 = (const float*)d_in[6];
    const float* W3 = (const float*)d_in[7];
    const float* b3 = (const float*)d_in[8];
    const float* Wp = (const float*)d_in[9];
    const float* bp = (const float*)d_in[10];
    const float* Wv = (const float*)d_in[11];
    const float* bv = (const float*)d_in[12];
    float* out = (float*)d_out;

    void *pX16_, *pAgg_, *pW16_;
    cudaGetSymbolAddress(&pX16_, g_x16);
    cudaGetSymbolAddress(&pAgg_, g_agg16);
    cudaGetSymbolAddress(&pW16_, g_w16);
    __half* x16 = (__half*)pX16_;
    __half* agg16 = (__half*)pAgg_;
    __half* w16 = (__half*)pW16_;

    // graph preprocessing (order-free CSR; head constants folded in)
    zero_kernel<<<(NN + 255) / 256, 256>>>(b3, Wp, Wv);
    count_conv_kernel<<<(CONV_TOTAL + 255) / 256, 256>>>(src, dst, features, W1, W2, W3);
    alloc_kernel<<<(NN + 255) / 256, 256>>>(bp, out);
    fill_kernel<<<(NE + 255) / 256, 256>>>(src, dst);

    dim3 ggrid((NN + MT - 1) / MT, 2);  // 63 x 2 = 126 CTAs

    // layer 1 (K=128)
    aggregate_kernel<1><<<1250, 256>>>(x16, agg16, 128);
    gemm_mma<<<ggrid, 256>>>(agg16, w16, b1, x16, Wp, Wv, out, 128, 0);
    // layer 2 (K=256)
    aggregate_kernel<2><<<1250, 256>>>(x16, agg16, 256);
    gemm_mma<<<ggrid, 256>>>(agg16, w16 + 32768, b2, x16, Wp, Wv, out, 256, 0);
    // layer 3 (K=256): fused heads epilogue
    aggregate_kernel<2><<<1250, 256>>>(x16, agg16, 256);
    gemm_mma<<<ggrid, 256>>>(agg16, w16 + 98304, b3, x16, Wp, Wv, out, 256, 1);

    final_kernel<<<1, 32>>>(bv, out);
}

// round 11
// speedup vs baseline: 1.3109x; 1.0259x over previous
#include <cuda_runtime.h>
#include <cuda_fp16.h>
#include <cstdint>

#define NN 10000
#define NE 320000
#define F_HID 256
#define EPT_T (NE / 4)   // 80000 edge-threads (4 edges each)

// ---------------- scratch (device globals; no allocation allowed) ----------------
__device__ int   g_deg[NN];
__device__ int   g_incnt[NN];
__device__ int   g_roff[NN];
__device__ int   g_rend[NN];
__device__ int   g_rank[NE];
__device__ int   g_total;
__device__ int   g_done;
__device__ float g_inv[NN];
__device__ int2  g_csr[NE];                          // (src, w bits)
__device__ __align__(16) __half g_x16[NN * F_HID];   // layer outputs / gather operand
__device__ __align__(16) __half g_agg16[NN * F_HID]; // agg output = GEMM A operand
__device__ __align__(16) __half g_w16[256 * 256 * 3];// fp16 weights
__device__ float g_vsum;
__device__ float g_dotp;   // b3 . Wp
__device__ float g_dotv;   // b3 . Wv

// ---------------- helpers ----------------
__device__ __forceinline__ void ldsm4(uint32_t* r, uint32_t addr) {
    asm volatile("ldmatrix.sync.aligned.m8n8.x4.shared.b16 {%0,%1,%2,%3}, [%4];"
                 : "=r"(r[0]), "=r"(r[1]), "=r"(r[2]), "=r"(r[3]) : "r"(addr));
}
__device__ __forceinline__ void ldsm4t(uint32_t* r, uint32_t addr) {
    asm volatile("ldmatrix.sync.aligned.m8n8.x4.trans.shared.b16 {%0,%1,%2,%3}, [%4];"
                 : "=r"(r[0]), "=r"(r[1]), "=r"(r[2]), "=r"(r[3]) : "r"(addr));
}
__device__ __forceinline__ void mma16816f(float* c, const uint32_t* a, const uint32_t* b) {
    asm volatile(
        "mma.sync.aligned.m16n8k16.row.col.f32.f16.f16.f32 "
        "{%0,%1,%2,%3}, {%4,%5,%6,%7}, {%8,%9}, {%0,%1,%2,%3};"
        : "+f"(c[0]), "+f"(c[1]), "+f"(c[2]), "+f"(c[3])
        : "r"(a[0]), "r"(a[1]), "r"(a[2]), "r"(a[3]), "r"(b[0]), "r"(b[1]));
}

// ---------------- count (4 edges/thread) + conversions + head dot constants ----------------
// NOTE: relies on g_deg/g_incnt being zero at entry (loader-zeroed initially;
// alloc_kernel re-zeros them every run, so the invariant self-maintains).
#define NFP (NN * 128 / 2)          // 640000
#define W1P (128 * 256 / 2)         // 16384
#define W2P (256 * 256 / 2)         // 32768
#define CONV_TOTAL (NFP + W1P + 2 * W2P)  // 721920
__global__ void count_conv_kernel(const int* __restrict__ src, const int* __restrict__ dst,
                                  const float* __restrict__ X, const float* __restrict__ W1,
                                  const float* __restrict__ W2, const float* __restrict__ W3,
                                  const float* __restrict__ b3, const float* __restrict__ Wp,
                                  const float* __restrict__ Wv) {
    int t = blockIdx.x * blockDim.x + threadIdx.x;
    if (t < EPT_T) {
        int s0 = src[t],             d0 = dst[t];
        int s1 = src[t + EPT_T],     d1 = dst[t + EPT_T];
        int s2 = src[t + 2 * EPT_T], d2 = dst[t + 2 * EPT_T];
        int s3 = src[t + 3 * EPT_T], d3 = dst[t + 3 * EPT_T];
        atomicAdd(&g_deg[s0], 1);
        atomicAdd(&g_deg[s1], 1);
        atomicAdd(&g_deg[s2], 1);
        atomicAdd(&g_deg[s3], 1);
        g_rank[t]             = atomicAdd(&g_incnt[d0], 1);
        g_rank[t + EPT_T]     = atomicAdd(&g_incnt[d1], 1);
        g_rank[t + 2 * EPT_T] = atomicAdd(&g_incnt[d2], 1);
        g_rank[t + 3 * EPT_T] = atomicAdd(&g_incnt[d3], 1);
    } else if (t - EPT_T < CONV_TOTAL) {
        int c = t - EPT_T;
        if (c < NFP) {
            float2 v = *(const float2*)(X + 2 * c);
            __half2 h = __floats2half2_rn(v.x, v.y);
            *(uint32_t*)((char*)g_x16 + 4 * c) = *reinterpret_cast<uint32_t*>(&h);
        } else {
            int u = c - NFP;
            const float* Wsrc;
            int off;
            if (u < W1P) { Wsrc = W1; off = 0; }
            else if (u < W1P + W2P) { Wsrc = W2; off = 32768; u -= W1P; }
            else { Wsrc = W3; off = 98304; u -= W1P + W2P; }
            float2 v = *(const float2*)(Wsrc + 2 * u);
            __half2 h = __floats2half2_rn(v.x, v.y);
            *(uint32_t*)((char*)g_w16 + 2 * (off + 2 * u)) = *reinterpret_cast<uint32_t*>(&h);
        }
    }
    // block 0 also computes b3.Wp / b3.Wv (whole block participates)
    if (blockIdx.x == 0) {
        __shared__ float sp[8], sv[8];
        int tt = threadIdx.x;  // 256
        float pd = b3[tt] * Wp[tt];
        float pv = b3[tt] * Wv[tt];
        #pragma unroll
        for (int o = 16; o > 0; o >>= 1) {
            pd += __shfl_xor_sync(0xffffffffu, pd, o);
            pv += __shfl_xor_sync(0xffffffffu, pv, o);
        }
        if ((tt & 31) == 0) { sp[tt >> 5] = pd; sv[tt >> 5] = pv; }
        __syncthreads();
        if (tt == 0) {
            float a = 0.f, b = 0.f;
            #pragma unroll
            for (int w = 0; w < 8; w++) { a += sp[w]; b += sv[w]; }
            g_dotp = a; g_dotv = b;
        }
    }
}

// order-free CSR bucket allocation + PI output init + counter re-zero for next run
__global__ void alloc_kernel(const float* __restrict__ bp, float* __restrict__ out) {
    int i = blockIdx.x * blockDim.x + threadIdx.x;
    if (i < NN) {
        int c = g_incnt[i];
        int base = atomicAdd(&g_total, c);
        g_roff[i] = base;
        g_rend[i] = base + c;
        int d = g_deg[i];
        g_inv[i] = (d > 0) ? 1.0f / (float)d : 0.0f;
        out[i] = bp[0] + g_dotp;
        g_incnt[i] = 0;   // restore invariant for next run
        g_deg[i] = 0;
    }
}

// fill CSR, 4 edges per thread (independent chains, MLP >= 4)
__global__ void fill_kernel(const int* __restrict__ src, const int* __restrict__ dst) {
    int t = blockIdx.x * blockDim.x + threadIdx.x;
    if (t < EPT_T) {
        int e[4] = { t, t + EPT_T, t + 2 * EPT_T, t + 3 * EPT_T };
        int s[4], d[4], r[4];
        #pragma unroll
        for (int q = 0; q < 4; q++) { s[q] = src[e[q]]; d[q] = dst[e[q]]; r[q] = g_rank[e[q]]; }
        int p[4];
        float w[4];
        #pragma unroll
        for (int q = 0; q < 4; q++) { p[q] = g_roff[d[q]] + r[q]; w[q] = g_inv[s[q]]; }
        #pragma unroll
        for (int q = 0; q < 4; q++)
            g_csr[p[q]] = make_int2(s[q], __float_as_int(w[q]));
    }
}

// ---------------- edge aggregation (fp16 gather, fp32 accum, MLP=8) -> fp16 ----------------
template <int CHUNKS>  // 1: F=128, 2: F=256
__global__ void aggregate_kernel(const __half* __restrict__ X,
                                 __half* __restrict__ Y, int F) {
    int gw    = (blockIdx.x * blockDim.x + threadIdx.x) >> 5;
    int lane  = threadIdx.x & 31;
    int nwrp  = (gridDim.x * blockDim.x) >> 5;
    for (int n = gw; n < NN; n += nwrp) {
        int s0 = g_roff[n], s1 = g_rend[n];
        float4 acc0 = make_float4(0.f, 0.f, 0.f, 0.f);
        float4 acc1 = make_float4(0.f, 0.f, 0.f, 0.f);
        for (int e0 = s0; e0 < s1; e0 += 32) {
            int   ss = 0; float ww = 0.f;
            if (e0 + lane < s1) {
                int2 ev = g_csr[e0 + lane];
                ss = ev.x; ww = __int_as_float(ev.y);
            }
            int cnt = min(32, s1 - e0);
            int j = 0;
            for (; j + 8 <= cnt; j += 8) {
                int   sj[8];
                float wj[8];
                #pragma unroll
                for (int q = 0; q < 8; q++) {
                    sj[q] = __shfl_sync(0xffffffffu, ss, j + q);
                    wj[q] = __shfl_sync(0xffffffffu, ww, j + q);
                }
                if (CHUNKS == 1) {
                    uint2 v[8];
                    #pragma unroll
                    for (int q = 0; q < 8; q++)
                        v[q] = ((const uint2*)(X + (size_t)sj[q] * F))[lane];
                    #pragma unroll
                    for (int q = 0; q < 8; q++) {
                        float2 f0 = __half22float2(*reinterpret_cast<__half2*>(&v[q].x));
                        float2 f1 = __half22float2(*reinterpret_cast<__half2*>(&v[q].y));
                        acc0.x += wj[q] * f0.x; acc0.y += wj[q] * f0.y;
                        acc0.z += wj[q] * f1.x; acc0.w += wj[q] * f1.y;
                    }
                } else {
                    uint4 v[8];
                    #pragma unroll
                    for (int q = 0; q < 8; q++)
                        v[q] = ((const uint4*)(X + (size_t)sj[q] * F))[lane];
                    #pragma unroll
                    for (int q = 0; q < 8; q++) {
                        float2 f0 = __half22float2(*reinterpret_cast<__half2*>(&v[q].x));
                        float2 f1 = __half22float2(*reinterpret_cast<__half2*>(&v[q].y));
                        float2 f2 = __half22float2(*reinterpret_cast<__half2*>(&v[q].z));
                        float2 f3 = __half22float2(*reinterpret_cast<__half2*>(&v[q].w));
                        acc0.x += wj[q] * f0.x; acc0.y += wj[q] * f0.y;
                        acc0.z += wj[q] * f1.x; acc0.w += wj[q] * f1.y;
                        acc1.x += wj[q] * f2.x; acc1.y += wj[q] * f2.y;
                        acc1.z += wj[q] * f3.x; acc1.w += wj[q] * f3.y;
                    }
                }
            }
            for (; j < cnt; j++) {
                int   sj = __shfl_sync(0xffffffffu, ss, j);
                float wj = __shfl_sync(0xffffffffu, ww, j);
                if (CHUNKS == 1) {
                    uint2 v = ((const uint2*)(X + (size_t)sj * F))[lane];
                    float2 f0 = __half22float2(*reinterpret_cast<__half2*>(&v.x));
                    float2 f1 = __half22float2(*reinterpret_cast<__half2*>(&v.y));
                    acc0.x += wj * f0.x; acc0.y += wj * f0.y;
                    acc0.z += wj * f1.x; acc0.w += wj * f1.y;
                } else {
                    uint4 v = ((const uint4*)(X + (size_t)sj * F))[lane];
                    float2 f0 = __half22float2(*reinterpret_cast<__half2*>(&v.x));
                    float2 f1 = __half22float2(*reinterpret_cast<__half2*>(&v.y));
                    float2 f2 = __half22float2(*reinterpret_cast<__half2*>(&v.z));
                    float2 f3 = __half22float2(*reinterpret_cast<__half2*>(&v.w));
                    acc0.x += wj * f0.x; acc0.y += wj * f0.y;
                    acc0.z += wj * f1.x; acc0.w += wj * f1.y;
                    acc1.x += wj * f2.x; acc1.y += wj * f2.y;
                    acc1.z += wj * f3.x; acc1.w += wj * f3.y;
                }
            }
        }
        __half2 p0 = __floats2half2_rn(acc0.x, acc0.y);
        __half2 p1 = __floats2half2_rn(acc0.z, acc0.w);
        if (CHUNKS == 1) {
            ((uint2*)(Y + (size_t)n * F))[lane] =
                make_uint2(*reinterpret_cast<uint32_t*>(&p0), *reinterpret_cast<uint32_t*>(&p1));
        } else {
            __half2 p2 = __floats2half2_rn(acc1.x, acc1.y);
            __half2 p3 = __floats2half2_rn(acc1.z, acc1.w);
            ((uint4*)(Y + (size_t)n * F))[lane] =
                make_uint4(*reinterpret_cast<uint32_t*>(&p0), *reinterpret_cast<uint32_t*>(&p1),
                           *reinterpret_cast<uint32_t*>(&p2), *reinterpret_cast<uint32_t*>(&p3));
        }
    }
}

// ---------------- GEMM via mma.sync fp16 (single product) ----------------
// CTA tile 160x128, 8 warps (2m x 4n), warp tile 80x32, BK=32 -> 126 CTAs (single wave)
// mode 0: relu + fp16 out (C16)
// mode 1: fused heads epilogue + final V write by last-finishing CTA
#define MT 160
#define AS_STRIDE 40
#define BS_STRIDE 136
__global__ void __launch_bounds__(256)
gemm_mma(const __half* __restrict__ A, const __half* __restrict__ W16,
         const float* __restrict__ bias, __half* __restrict__ C16,
         const float* __restrict__ Wp, const float* __restrict__ Wv,
         const float* __restrict__ bv, float* __restrict__ out, int K, int mode) {
    __shared__ __align__(16) __half sA[MT * AS_STRIDE];
    __shared__ __align__(16) __half sB[32 * BS_STRIDE];
    __shared__ float sbias[128];
    __shared__ float spi[MT];
    __shared__ float svred[8];

    int tid = threadIdx.x;
    int m0 = blockIdx.x * MT, n0 = blockIdx.y * 128;
    if (tid < 128) sbias[tid] = bias[n0 + tid];
    int wid = tid >> 5, lane = tid & 31;
    int wm = (wid & 1) * 80, wn = (wid >> 1) * 32;

    float acc[5][4][4];
    #pragma unroll
    for (int i = 0; i < 5; i++)
        #pragma unroll
        for (int j = 0; j < 4; j++)
            #pragma unroll
            for (int q = 0; q < 4; q++) acc[i][j][q] = 0.f;

    const uint4 z4 = make_uint4(0, 0, 0, 0);

    for (int kc = 0; kc < K; kc += 32) {
        #pragma unroll
        for (int idx = tid; idx < MT * 4; idx += 256) {
            int row = idx >> 2, c16 = idx & 3;
            int gr = m0 + row;
            uint4 vh = z4;
            if (gr < NN)
                vh = *(const uint4*)(A + (size_t)gr * K + kc + c16 * 8);
            *(uint4*)(sA + row * AS_STRIDE + c16 * 8) = vh;
        }
        #pragma unroll
        for (int idx = tid; idx < 512; idx += 256) {
            int row = idx >> 4, c16 = idx & 15;
            *(uint4*)(sB + row * BS_STRIDE + c16 * 8) =
                *(const uint4*)(W16 + (size_t)(kc + row) * 256 + n0 + c16 * 8);
        }
        __syncthreads();

        #pragma unroll
        for (int k16 = 0; k16 < 2; k16++) {
            uint32_t ah[5][4], bh[4][2];
            #pragma unroll
            for (int mt = 0; mt < 5; mt++) {
                int row = wm + mt * 16 + (lane & 15);
                int col = k16 * 16 + (lane >> 4) * 8;
                uint32_t ad = (uint32_t)__cvta_generic_to_shared(sA + row * AS_STRIDE + col);
                ldsm4(ah[mt], ad);
            }
            #pragma unroll
            for (int nt2 = 0; nt2 < 2; nt2++) {
                int row = k16 * 16 + (lane & 15);
                int col = wn + nt2 * 16 + ((lane >> 4) & 1) * 8;
                uint32_t t[4];
                uint32_t ad = (uint32_t)__cvta_generic_to_shared(sB + row * BS_STRIDE + col);
                ldsm4t(t, ad);
                bh[nt2 * 2][0] = t[0]; bh[nt2 * 2][1] = t[1];
                bh[nt2 * 2 + 1][0] = t[2]; bh[nt2 * 2 + 1][1] = t[3];
            }
            #pragma unroll
            for (int mt = 0; mt < 5; mt++)
                #pragma unroll
                for (int nt = 0; nt < 4; nt++)
                    mma16816f(acc[mt][nt], ah[mt], bh[nt]);
        }
        __syncthreads();
    }

    if (mode == 0) {
        #pragma unroll
        for (int mt = 0; mt < 5; mt++) {
            int r0 = m0 + wm + mt * 16 + (lane >> 2);
            int r1 = r0 + 8;
            #pragma unroll
            for (int nt = 0; nt < 4; nt++) {
                int cl = wn + nt * 8 + (lane & 3) * 2;
                float b0 = sbias[cl], b1 = sbias[cl + 1];
                float v0 = fmaxf(acc[mt][nt][0] + b0, 0.f);
                float v1 = fmaxf(acc[mt][nt][1] + b1, 0.f);
                float v2 = fmaxf(acc[mt][nt][2] + b0, 0.f);
                float v3 = fmaxf(acc[mt][nt][3] + b1, 0.f);
                if (r0 < NN)
                    *(__half2*)(C16 + (size_t)r0 * 256 + n0 + cl) = __floats2half2_rn(v0, v1);
                if (r1 < NN)
                    *(__half2*)(C16 + (size_t)r1 * 256 + n0 + cl) = __floats2half2_rn(v2, v3);
            }
        }
    } else {
        float wp[8], wv[8];
        #pragma unroll
        for (int nt = 0; nt < 4; nt++) {
            int cg = n0 + wn + nt * 8 + (lane & 3) * 2;
            wp[nt * 2] = Wp[cg]; wp[nt * 2 + 1] = Wp[cg + 1];
            wv[nt * 2] = Wv[cg]; wv[nt * 2 + 1] = Wv[cg + 1];
        }
        for (int i = tid; i < MT; i += 256) spi[i] = 0.f;
        __syncthreads();
        float vth = 0.f;
        #pragma unroll
        for (int mt = 0; mt < 5; mt++) {
            float p0 = 0.f, p1 = 0.f, q0 = 0.f, q1 = 0.f;
            #pragma unroll
            for (int nt = 0; nt < 4; nt++) {
                p0 += acc[mt][nt][0] * wp[nt * 2] + acc[mt][nt][1] * wp[nt * 2 + 1];
                p1 += acc[mt][nt][2] * wp[nt * 2] + acc[mt][nt][3] * wp[nt * 2 + 1];
                q0 += acc[mt][nt][0] * wv[nt * 2] + acc[mt][nt][1] * wv[nt * 2 + 1];
                q1 += acc[mt][nt][2] * wv[nt * 2] + acc[mt][nt][3] * wv[nt * 2 + 1];
            }
            #pragma unroll
            for (int o = 1; o <= 2; o <<= 1) {
                p0 += __shfl_xor_sync(0xffffffffu, p0, o);
                p1 += __shfl_xor_sync(0xffffffffu, p1, o);
                q0 += __shfl_xor_sync(0xffffffffu, q0, o);
                q1 += __shfl_xor_sync(0xffffffffu, q1, o);
            }
            if ((lane & 3) == 0) {
                int lr = wm + mt * 16 + (lane >> 2);
                atomicAdd(&spi[lr], p0);
                atomicAdd(&spi[lr + 8], p1);
                vth += q0 + q1;
            }
        }
        #pragma unroll
        for (int o = 16; o > 0; o >>= 1) vth += __shfl_xor_sync(0xffffffffu, vth, o);
        if (lane == 0) svred[wid] = vth;
        __syncthreads();
        for (int i = tid; i < MT; i += 256) {
            int gr = m0 + i;
            if (gr < NN) atomicAdd(&out[gr], spi[i]);
        }
        if (tid == 0) {
            float s = 0.f;
            #pragma unroll
            for (int w = 0; w < 8; w++) s += svred[w];
            atomicAdd(&g_vsum, s);
            __threadfence();
            int ncta = (int)(gridDim.x * gridDim.y);
            int ticket = atomicAdd(&g_done, 1);
            if (ticket == ncta - 1) {
                // last CTA: all g_vsum contributions visible (fence-before-ticket)
                out[NN] = g_vsum * (1.0f / (float)NN) + g_dotv + bv[0];
                g_vsum = 0.0f;   // restore invariants for next run
                g_total = 0;
                g_done = 0;
            }
        }
    }
}

// ---------------- launch ----------------
extern "C" void kernel_launch(void* const* d_in, const int* in_sizes, int n_in,
                              void* d_out, int out_size) {
    const float* features = (const float*)d_in[0];
    const int*   src      = (const int*)d_in[1];
    const int*   dst      = (const int*)d_in[2];
    const float* W1 = (const float*)d_in[3];
    const float* b1 = (const float*)d_in[4];
    const float* W2 = (const float*)d_in[5];
    const float* b2 = (const float*)d_in[6];
    const float* W3 = (const float*)d_in[7];
    const float* b3 = (const float*)d_in[8];
    const float* Wp = (const float*)d_in[9];
    const float* bp = (const float*)d_in[10];
    const float* Wv = (const float*)d_in[11];
    const float* bv = (const float*)d_in[12];
    float* out = (float*)d_out;

    void *pX16_, *pAgg_, *pW16_;
    cudaGetSymbolAddress(&pX16_, g_x16);
    cudaGetSymbolAddress(&pAgg_, g_agg16);
    cudaGetSymbolAddress(&pW16_, g_w16);
    __half* x16 = (__half*)pX16_;
    __half* agg16 = (__half*)pAgg_;
    __half* w16 = (__half*)pW16_;

    // preprocessing: count(4 edges/thr) + conversions + head dots, then alloc, then fill
    int cc_threads = EPT_T + CONV_TOTAL;
    count_conv_kernel<<<(cc_threads + 255) / 256, 256>>>(src, dst, features, W1, W2, W3,
                                                         b3, Wp, Wv);
    alloc_kernel<<<(NN + 255) / 256, 256>>>(bp, out);
    fill_kernel<<<(EPT_T + 255) / 256, 256>>>(src, dst);

    dim3 ggrid((NN + MT - 1) / MT, 2);  // 63 x 2 = 126 CTAs

    // layer 1 (K=128)
    aggregate_kernel<1><<<1250, 256>>>(x16, agg16, 128);
    gemm_mma<<<ggrid, 256>>>(agg16, w16, b1, x16, Wp, Wv, bv, out, 128, 0);
    // layer 2 (K=256)
    aggregate_kernel<2><<<1250, 256>>>(x16, agg16, 256);
    gemm_mma<<<ggrid, 256>>>(agg16, w16 + 32768, b2, x16, Wp, Wv, bv, out, 256, 0);
    // layer 3 (K=256): fused heads epilogue + final V write
    aggregate_kernel<2><<<1250, 256>>>(x16, agg16, 256);
    gemm_mma<<<ggrid, 256>>>(agg16, w16 + 98304, b3, x16, Wp, Wv, bv, out, 256, 1);
}

// round 15
// speedup vs baseline: 1.5474x; 1.1804x over previous
#include <cuda_runtime.h>
#include <cuda_fp16.h>
#include <cstdint>

#define NN 10000
#define NE 320000
#define F_HID 256
#define EPT_T (NE / 4)   // 80000 edge-threads (4 edges each)

// ---------------- scratch (device globals; no allocation allowed) ----------------
__device__ int   g_deg[NN];
__device__ int   g_incnt[NN];
__device__ int   g_roff[NN];
__device__ int   g_rend[NN];
__device__ int   g_rank[NE];
__device__ int   g_total;
__device__ float g_inv[NN];
__device__ int   g_csr[NE];                                   // src only (premultiplied msgs)
__device__ float g_y[NN];                                     // y'[s] = (x2[s].u) * inv[s]
__device__ float g_u[256];                                    // W3 . Wp
__device__ float g_t[256];                                    // W3 . Wv
__device__ __align__(16) __half g_x16[NN * F_HID];            // premultiplied fp16 gather operand
__device__ __align__(16) __half g_agg16[NN * F_HID];          // agg output = GEMM A operand
__device__ __align__(16) __half g_whi[256 * 256 * 2];         // fp16 hi of W1,W2
__device__ __align__(16) __half g_wlo[256 * 256 * 2];         // fp16 lo of W1,W2
__device__ float g_vsum;
__device__ float g_dotp;   // b3 . Wp
__device__ float g_dotv;   // b3 . Wv

// ---------------- helpers ----------------
__device__ __forceinline__ void ldsm4(uint32_t* r, uint32_t addr) {
    asm volatile("ldmatrix.sync.aligned.m8n8.x4.shared.b16 {%0,%1,%2,%3}, [%4];"
                 : "=r"(r[0]), "=r"(r[1]), "=r"(r[2]), "=r"(r[3]) : "r"(addr));
}
__device__ __forceinline__ void ldsm4t(uint32_t* r, uint32_t addr) {
    asm volatile("ldmatrix.sync.aligned.m8n8.x4.trans.shared.b16 {%0,%1,%2,%3}, [%4];"
                 : "=r"(r[0]), "=r"(r[1]), "=r"(r[2]), "=r"(r[3]) : "r"(addr));
}
__device__ __forceinline__ void mma16816f(float* c, const uint32_t* a, const uint32_t* b) {
    asm volatile(
        "mma.sync.aligned.m16n8k16.row.col.f32.f16.f16.f32 "
        "{%0,%1,%2,%3}, {%4,%5,%6,%7}, {%8,%9}, {%0,%1,%2,%3};"
        : "+f"(c[0]), "+f"(c[1]), "+f"(c[2]), "+f"(c[3])
        : "r"(a[0]), "r"(a[1]), "r"(a[2]), "r"(a[3]), "r"(b[0]), "r"(b[1]));
}

// ---------------- count (4 edges/thread) + W hi/lo conversion + u/t matvec + head dots ----------------
// relies on g_deg/g_incnt zero at entry (loader-zeroed; alloc_kernel re-zeros each run)
#define NFP (NN * 128 / 2)          // 640000 feature pairs
#define W1P (128 * 256 / 2)         // 16384
#define W2P (256 * 256 / 2)         // 32768
#define WCONV (W1P + W2P)           // 49152 (W1 + W2)
#define UT_BASE (EPT_T + WCONV)     // 129152 (warp-aligned)
#define CC_TOTAL (UT_BASE + 8192)
__global__ void count_conv_kernel(const int* __restrict__ src, const int* __restrict__ dst,
                                  const float* __restrict__ W1, const float* __restrict__ W2,
                                  const float* __restrict__ W3, const float* __restrict__ b3,
                                  const float* __restrict__ Wp, const float* __restrict__ Wv) {
    int t = blockIdx.x * blockDim.x + threadIdx.x;
    if (t < EPT_T) {
        int s0 = src[t],             d0 = dst[t];
        int s1 = src[t + EPT_T],     d1 = dst[t + EPT_T];
        int s2 = src[t + 2 * EPT_T], d2 = dst[t + 2 * EPT_T];
        int s3 = src[t + 3 * EPT_T], d3 = dst[t + 3 * EPT_T];
        atomicAdd(&g_deg[s0], 1);
        atomicAdd(&g_deg[s1], 1);
        atomicAdd(&g_deg[s2], 1);
        atomicAdd(&g_deg[s3], 1);
        g_rank[t]             = atomicAdd(&g_incnt[d0], 1);
        g_rank[t + EPT_T]     = atomicAdd(&g_incnt[d1], 1);
        g_rank[t + 2 * EPT_T] = atomicAdd(&g_incnt[d2], 1);
        g_rank[t + 3 * EPT_T] = atomicAdd(&g_incnt[d3], 1);
    } else if (t < UT_BASE) {
        int u = t - EPT_T;
        const float* Wsrc;
        int off;
        if (u < W1P) { Wsrc = W1; off = 0; }
        else { Wsrc = W2; off = 32768; u -= W1P; }
        float2 v = *(const float2*)(Wsrc + 2 * u);
        __half2 h = __floats2half2_rn(v.x, v.y);
        float hx = __half2float(__low2half(h));
        float hy = __half2float(__high2half(h));
        __half2 l = __floats2half2_rn(v.x - hx, v.y - hy);
        *(uint32_t*)((char*)g_whi + 2 * (off + 2 * u)) = *reinterpret_cast<uint32_t*>(&h);
        *(uint32_t*)((char*)g_wlo + 2 * (off + 2 * u)) = *reinterpret_cast<uint32_t*>(&l);
    } else if (t < CC_TOTAL) {
        // u/t matvec: warp w computes u[w] = W3[w].Wp, t[w] = W3[w].Wv (fp32 exact)
        int w = (t - UT_BASE) >> 5;
        int ln = t & 31;
        float su = 0.f, st = 0.f;
        #pragma unroll
        for (int c = ln; c < 256; c += 32) {
            float w3 = W3[w * 256 + c];
            su += w3 * Wp[c];
            st += w3 * Wv[c];
        }
        #pragma unroll
        for (int o = 16; o > 0; o >>= 1) {
            su += __shfl_xor_sync(0xffffffffu, su, o);
            st += __shfl_xor_sync(0xffffffffu, st, o);
        }
        if (ln == 0) { g_u[w] = su; g_t[w] = st; }
    }
    if (blockIdx.x == 0) {
        __shared__ float sp[8], sv[8];
        int tt = threadIdx.x;  // 256
        float pd = b3[tt] * Wp[tt];
        float pv = b3[tt] * Wv[tt];
        #pragma unroll
        for (int o = 16; o > 0; o >>= 1) {
            pd += __shfl_xor_sync(0xffffffffu, pd, o);
            pv += __shfl_xor_sync(0xffffffffu, pv, o);
        }
        if ((tt & 31) == 0) { sp[tt >> 5] = pd; sv[tt >> 5] = pv; }
        __syncthreads();
        if (tt == 0) {
            float a = 0.f, b = 0.f;
            #pragma unroll
            for (int w = 0; w < 8; w++) { a += sp[w]; b += sv[w]; }
            g_dotp = a; g_dotv = b;
        }
    }
}

// order-free CSR bucket allocation + PI const init + y/vsum zero + counter re-zero
__global__ void alloc_kernel(const float* __restrict__ bp, float* __restrict__ out) {
    int i = blockIdx.x * blockDim.x + threadIdx.x;
    if (i < NN) {
        int c = g_incnt[i];
        int base = atomicAdd(&g_total, c);
        g_roff[i] = base;
        g_rend[i] = base + c;
        int d = g_deg[i];
        g_inv[i] = (d > 0) ? 1.0f / (float)d : 0.0f;
        out[i] = bp[0] + g_dotp;   // PI constant: b3.Wp + bp
        g_y[i] = 0.f;
        g_incnt[i] = 0;
        g_deg[i] = 0;
        if (i == 0) g_vsum = 0.f;
    }
}

// fill CSR (4 edges/thread) + premultiplied fp16 feature conversion (needs g_inv)
__global__ void fill_kernel(const int* __restrict__ src, const int* __restrict__ dst,
                            const float* __restrict__ X) {
    int t = blockIdx.x * blockDim.x + threadIdx.x;
    if (t < EPT_T) {
        int e[4] = { t, t + EPT_T, t + 2 * EPT_T, t + 3 * EPT_T };
        int s[4], d[4], r[4];
        #pragma unroll
        for (int q = 0; q < 4; q++) { s[q] = src[e[q]]; d[q] = dst[e[q]]; r[q] = g_rank[e[q]]; }
        int p[4];
        #pragma unroll
        for (int q = 0; q < 4; q++) p[q] = g_roff[d[q]] + r[q];
        #pragma unroll
        for (int q = 0; q < 4; q++) g_csr[p[q]] = s[q];
    } else if (t - EPT_T < NFP) {
        int c = t - EPT_T;               // feature pair index
        int node = c >> 6;               // 64 pairs per node (F=128)
        float iv = g_inv[node];
        float2 v = *(const float2*)(X + 2 * c);
        __half2 h = __floats2half2_rn(v.x * iv, v.y * iv);
        *(uint32_t*)((char*)g_x16 + 4 * c) = *reinterpret_cast<uint32_t*>(&h);
    }
}

// ---------------- edge aggregation: unweighted sum of premultiplied fp16 rows ----------------
template <int CHUNKS>  // 1: F=128 (uint2/lane, MLP 8), 2: F=256 (uint4/lane, MLP 4)
__global__ void aggregate_kernel(const __half* __restrict__ X,
                                 __half* __restrict__ Y, int F) {
    int gw    = (blockIdx.x * blockDim.x + threadIdx.x) >> 5;
    int lane  = threadIdx.x & 31;
    int nwrp  = (gridDim.x * blockDim.x) >> 5;
    const int ROWB = F * 2;
    const char* Xb = (const char*)X + lane * (CHUNKS == 1 ? 8 : 16);
    for (int n = gw; n < NN; n += nwrp) {
        int s0 = g_roff[n], s1 = g_rend[n];
        float4 acc0 = make_float4(0.f, 0.f, 0.f, 0.f);
        float4 acc1 = make_float4(0.f, 0.f, 0.f, 0.f);
        for (int e0 = s0; e0 < s1; e0 += 32) {
            uint32_t offl = 0;
            if (e0 + lane < s1) offl = (uint32_t)g_csr[e0 + lane] * ROWB;
            int cnt = min(32, s1 - e0);
            int j = 0;
            if (CHUNKS == 1) {
                for (; j + 8 <= cnt; j += 8) {
                    uint32_t of[8];
                    #pragma unroll
                    for (int q = 0; q < 8; q++)
                        of[q] = __shfl_sync(0xffffffffu, offl, j + q);
                    uint2 v[8];
                    #pragma unroll
                    for (int q = 0; q < 8; q++)
                        v[q] = *(const uint2*)(Xb + of[q]);
                    #pragma unroll
                    for (int q = 0; q < 8; q++) {
                        float2 f0 = __half22float2(*reinterpret_cast<__half2*>(&v[q].x));
                        float2 f1 = __half22float2(*reinterpret_cast<__half2*>(&v[q].y));
                        acc0.x += f0.x; acc0.y += f0.y;
                        acc0.z += f1.x; acc0.w += f1.y;
                    }
                }
                for (; j < cnt; j++) {
                    uint32_t of = __shfl_sync(0xffffffffu, offl, j);
                    uint2 v = *(const uint2*)(Xb + of);
                    float2 f0 = __half22float2(*reinterpret_cast<__half2*>(&v.x));
                    float2 f1 = __half22float2(*reinterpret_cast<__half2*>(&v.y));
                    acc0.x += f0.x; acc0.y += f0.y;
                    acc0.z += f1.x; acc0.w += f1.y;
                }
            } else {
                for (; j + 4 <= cnt; j += 4) {
                    uint32_t of[4];
                    #pragma unroll
                    for (int q = 0; q < 4; q++)
                        of[q] = __shfl_sync(0xffffffffu, offl, j + q);
                    uint4 v[4];
                    #pragma unroll
                    for (int q = 0; q < 4; q++)
                        v[q] = *(const uint4*)(Xb + of[q]);
                    #pragma unroll
                    for (int q = 0; q < 4; q++) {
                        float2 f0 = __half22float2(*reinterpret_cast<__half2*>(&v[q].x));
                        float2 f1 = __half22float2(*reinterpret_cast<__half2*>(&v[q].y));
                        float2 f2 = __half22float2(*reinterpret_cast<__half2*>(&v[q].z));
                        float2 f3 = __half22float2(*reinterpret_cast<__half2*>(&v[q].w));
                        acc0.x += f0.x; acc0.y += f0.y;
                        acc0.z += f1.x; acc0.w += f1.y;
                        acc1.x += f2.x; acc1.y += f2.y;
                        acc1.z += f3.x; acc1.w += f3.y;
                    }
                }
                for (; j < cnt; j++) {
                    uint32_t of = __shfl_sync(0xffffffffu, offl, j);
                    uint4 v = *(const uint4*)(Xb + of);
                    float2 f0 = __half22float2(*reinterpret_cast<__half2*>(&v.x));
                    float2 f1 = __half22float2(*reinterpret_cast<__half2*>(&v.y));
                    float2 f2 = __half22float2(*reinterpret_cast<__half2*>(&v.z));
                    float2 f3 = __half22float2(*reinterpret_cast<__half2*>(&v.w));
                    acc0.x += f0.x; acc0.y += f0.y;
                    acc0.z += f1.x; acc0.w += f1.y;
                    acc1.x += f2.x; acc1.y += f2.y;
                    acc1.z += f3.x; acc1.w += f3.y;
                }
            }
        }
        __half2 p0 = __floats2half2_rn(acc0.x, acc0.y);
        __half2 p1 = __floats2half2_rn(acc0.z, acc0.w);
        if (CHUNKS == 1) {
            ((uint2*)(Y + (size_t)n * F))[lane] =
                make_uint2(*reinterpret_cast<uint32_t*>(&p0), *reinterpret_cast<uint32_t*>(&p1));
        } else {
            __half2 p2 = __floats2half2_rn(acc1.x, acc1.y);
            __half2 p3 = __floats2half2_rn(acc1.z, acc1.w);
            ((uint4*)(Y + (size_t)n * F))[lane] =
                make_uint4(*reinterpret_cast<uint32_t*>(&p0), *reinterpret_cast<uint32_t*>(&p1),
                           *reinterpret_cast<uint32_t*>(&p2), *reinterpret_cast<uint32_t*>(&p3));
        }
    }
}

// ---------------- GEMM via mma.sync fp16 with W hi/lo (2 products) ----------------
// CTA tile 160x128, 8 warps (2m x 4n), warp tile 80x32, BK=32 -> 126 CTAs
// mode 0: layer 1 — relu, premultiply by inv_deg, write fp16 gather operand
// mode 2: layer 2 — relu in registers, emit y'[row] = (x2.u)*inv and V partial (x2.t, deg>0)
#define MT 160
#define AS_STRIDE 40
#define BS_STRIDE 136
__global__ void __launch_bounds__(256)
gemm_mma(const __half* __restrict__ A, const __half* __restrict__ Whi,
         const __half* __restrict__ Wlo, const float* __restrict__ bias,
         __half* __restrict__ XH, int K, int mode) {
    __shared__ __align__(16) __half sA[MT * AS_STRIDE];
    __shared__ __align__(16) __half sBhi[32 * BS_STRIDE];
    __shared__ __align__(16) __half sBlo[32 * BS_STRIDE];
    __shared__ float sbias[128];
    __shared__ float spi[MT];
    __shared__ float svred[8];

    int tid = threadIdx.x;
    int m0 = blockIdx.x * MT, n0 = blockIdx.y * 128;
    if (tid < 128) sbias[tid] = bias[n0 + tid];
    int wid = tid >> 5, lane = tid & 31;
    int wm = (wid & 1) * 80, wn = (wid >> 1) * 32;

    float acc[5][4][4];
    #pragma unroll
    for (int i = 0; i < 5; i++)
        #pragma unroll
        for (int j = 0; j < 4; j++)
            #pragma unroll
            for (int q = 0; q < 4; q++) acc[i][j][q] = 0.f;

    const uint4 z4 = make_uint4(0, 0, 0, 0);

    for (int kc = 0; kc < K; kc += 32) {
        #pragma unroll
        for (int idx = tid; idx < MT * 4; idx += 256) {
            int row = idx >> 2, c16 = idx & 3;
            int gr = m0 + row;
            uint4 vh = z4;
            if (gr < NN)
                vh = *(const uint4*)(A + (size_t)gr * K + kc + c16 * 8);
            *(uint4*)(sA + row * AS_STRIDE + c16 * 8) = vh;
        }
        #pragma unroll
        for (int idx = tid; idx < 512; idx += 256) {
            int row = idx >> 4, c16 = idx & 15;
            size_t goff = (size_t)(kc + row) * 256 + n0 + c16 * 8;
            *(uint4*)(sBhi + row * BS_STRIDE + c16 * 8) = *(const uint4*)(Whi + goff);
            *(uint4*)(sBlo + row * BS_STRIDE + c16 * 8) = *(const uint4*)(Wlo + goff);
        }
        __syncthreads();

        #pragma unroll
        for (int k16 = 0; k16 < 2; k16++) {
            uint32_t ah[5][4], bh[4][2], bl[4][2];
            #pragma unroll
            for (int mt = 0; mt < 5; mt++) {
                int row = wm + mt * 16 + (lane & 15);
                int col = k16 * 16 + (lane >> 4) * 8;
                uint32_t ad = (uint32_t)__cvta_generic_to_shared(sA + row * AS_STRIDE + col);
                ldsm4(ah[mt], ad);
            }
            #pragma unroll
            for (int nt2 = 0; nt2 < 2; nt2++) {
                int row = k16 * 16 + (lane & 15);
                int col = wn + nt2 * 16 + ((lane >> 4) & 1) * 8;
                uint32_t t[4];
                uint32_t ad = (uint32_t)__cvta_generic_to_shared(sBhi + row * BS_STRIDE + col);
                ldsm4t(t, ad);
                bh[nt2 * 2][0] = t[0]; bh[nt2 * 2][1] = t[1];
                bh[nt2 * 2 + 1][0] = t[2]; bh[nt2 * 2 + 1][1] = t[3];
                ad = (uint32_t)__cvta_generic_to_shared(sBlo + row * BS_STRIDE + col);
                ldsm4t(t, ad);
                bl[nt2 * 2][0] = t[0]; bl[nt2 * 2][1] = t[1];
                bl[nt2 * 2 + 1][0] = t[2]; bl[nt2 * 2 + 1][1] = t[3];
            }
            #pragma unroll
            for (int mt = 0; mt < 5; mt++)
                #pragma unroll
                for (int nt = 0; nt < 4; nt++) {
                    mma16816f(acc[mt][nt], ah[mt], bh[nt]);
                    mma16816f(acc[mt][nt], ah[mt], bl[nt]);
                }
        }
        __syncthreads();
    }

    if (mode == 0) {
        #pragma unroll
        for (int mt = 0; mt < 5; mt++) {
            int r0 = m0 + wm + mt * 16 + (lane >> 2);
            int r1 = r0 + 8;
            float i0 = (r0 < NN) ? g_inv[r0] : 0.f;
            float i1 = (r1 < NN) ? g_inv[r1] : 0.f;
            #pragma unroll
            for (int nt = 0; nt < 4; nt++) {
                int cl = wn + nt * 8 + (lane & 3) * 2;
                float b0 = sbias[cl], b1 = sbias[cl + 1];
                float v0 = fmaxf(acc[mt][nt][0] + b0, 0.f) * i0;
                float v1 = fmaxf(acc[mt][nt][1] + b1, 0.f) * i0;
                float v2 = fmaxf(acc[mt][nt][2] + b0, 0.f) * i1;
                float v3 = fmaxf(acc[mt][nt][3] + b1, 0.f) * i1;
                if (r0 < NN) {
                    __half2 h = __floats2half2_rn(v0, v1);
                    *(uint32_t*)(XH + (size_t)r0 * 256 + n0 + cl) = *reinterpret_cast<uint32_t*>(&h);
                }
                if (r1 < NN) {
                    __half2 h = __floats2half2_rn(v2, v3);
                    *(uint32_t*)(XH + (size_t)r1 * 256 + n0 + cl) = *reinterpret_cast<uint32_t*>(&h);
                }
            }
        }
    } else {
        // layer-2 fused: y' partial = relu(x2).u ; V partial = relu(x2).t (deg>0)
        float wu[8], wt[8];
        #pragma unroll
        for (int nt = 0; nt < 4; nt++) {
            int cg = n0 + wn + nt * 8 + (lane & 3) * 2;
            wu[nt * 2] = g_u[cg]; wu[nt * 2 + 1] = g_u[cg + 1];
            wt[nt * 2] = g_t[cg]; wt[nt * 2 + 1] = g_t[cg + 1];
        }
        for (int i = tid; i < MT; i += 256) spi[i] = 0.f;
        __syncthreads();
        float vth = 0.f;
        #pragma unroll
        for (int mt = 0; mt < 5; mt++) {
            int r0 = m0 + wm + mt * 16 + (lane >> 2);
            int r1 = r0 + 8;
            float i0 = (r0 < NN) ? g_inv[r0] : 0.f;
            float i1 = (r1 < NN) ? g_inv[r1] : 0.f;
            float p0 = 0.f, p1 = 0.f, q0 = 0.f, q1 = 0.f;
            #pragma unroll
            for (int nt = 0; nt < 4; nt++) {
                int cl = wn + nt * 8 + (lane & 3) * 2;
                float b0 = sbias[cl], b1 = sbias[cl + 1];
                float v0 = fmaxf(acc[mt][nt][0] + b0, 0.f);
                float v1 = fmaxf(acc[mt][nt][1] + b1, 0.f);
                float v2 = fmaxf(acc[mt][nt][2] + b0, 0.f);
                float v3 = fmaxf(acc[mt][nt][3] + b1, 0.f);
                p0 += v0 * wu[nt * 2] + v1 * wu[nt * 2 + 1];
                p1 += v2 * wu[nt * 2] + v3 * wu[nt * 2 + 1];
                q0 += v0 * wt[nt * 2] + v1 * wt[nt * 2 + 1];
                q1 += v2 * wt[nt * 2] + v3 * wt[nt * 2 + 1];
            }
            #pragma unroll
            for (int o = 1; o <= 2; o <<= 1) {
                p0 += __shfl_xor_sync(0xffffffffu, p0, o);
                p1 += __shfl_xor_sync(0xffffffffu, p1, o);
                q0 += __shfl_xor_sync(0xffffffffu, q0, o);
                q1 += __shfl_xor_sync(0xffffffffu, q1, o);
            }
            if ((lane & 3) == 0) {
                int lr = wm + mt * 16 + (lane >> 2);
                atomicAdd(&spi[lr], p0);
                atomicAdd(&spi[lr + 8], p1);
                vth += (i0 > 0.f ? q0 : 0.f) + (i1 > 0.f ? q1 : 0.f);
            }
        }
        #pragma unroll
        for (int o = 16; o > 0; o >>= 1) vth += __shfl_xor_sync(0xffffffffu, vth, o);
        if (lane == 0) svred[wid] = vth;
        __syncthreads();
        for (int i = tid; i < MT; i += 256) {
            int gr = m0 + i;
            if (gr < NN) atomicAdd(&g_y[gr], spi[i] * g_inv[gr]);
        }
        if (tid == 0) {
            float s = 0.f;
            #pragma unroll
            for (int w = 0; w < 8; w++) s += svred[w];
            atomicAdd(&g_vsum, s);
        }
    }
}

// ---------------- PI: scalar aggregation of y' over in-edges + final V write ----------------
__global__ void pi_kernel(const float* __restrict__ bv, float* __restrict__ out) {
    int gw   = (blockIdx.x * blockDim.x + threadIdx.x) >> 5;
    int lane = threadIdx.x & 31;
    int nwrp = (gridDim.x * blockDim.x) >> 5;
    for (int n = gw; n < NN; n += nwrp) {
        int s0 = g_roff[n], s1 = g_rend[n];
        float sum = 0.f;
        for (int e = s0 + lane; e < s1; e += 32)
            sum += g_y[g_csr[e]];
        #pragma unroll
        for (int o = 16; o > 0; o >>= 1)
            sum += __shfl_xor_sync(0xffffffffu, sum, o);
        if (lane == 0) out[n] += sum;
    }
    if (blockIdx.x == 0 && threadIdx.x == 0) {
        out[NN] = g_vsum * (1.0f / (float)NN) + g_dotv + bv[0];
        g_total = 0;   // restore invariant for next run
    }
}

// ---------------- launch ----------------
extern "C" void kernel_launch(void* const* d_in, const int* in_sizes, int n_in,
                              void* d_out, int out_size) {
    const float* features = (const float*)d_in[0];
    const int*   src      = (const int*)d_in[1];
    const int*   dst      = (const int*)d_in[2];
    const float* W1 = (const float*)d_in[3];
    const float* b1 = (const float*)d_in[4];
    const float* W2 = (const float*)d_in[5];
    const float* b2 = (const float*)d_in[6];
    const float* W3 = (const float*)d_in[7];
    const float* b3 = (const float*)d_in[8];
    const float* Wp = (const float*)d_in[9];
    const float* bp = (const float*)d_in[10];
    const float* Wv = (const float*)d_in[11];
    const float* bv = (const float*)d_in[12];
    float* out = (float*)d_out;

    void *pXH_, *pAgg_, *pWhi_, *pWlo_;
    cudaGetSymbolAddress(&pXH_, g_x16);
    cudaGetSymbolAddress(&pAgg_, g_agg16);
    cudaGetSymbolAddress(&pWhi_, g_whi);
    cudaGetSymbolAddress(&pWlo_, g_wlo);
    __half* xh = (__half*)pXH_;
    __half* agg16 = (__half*)pAgg_;
    __half* whi = (__half*)pWhi_;
    __half* wlo = (__half*)pWlo_;

    // preprocessing
    count_conv_kernel<<<(CC_TOTAL + 255) / 256, 256>>>(src, dst, W1, W2, W3, b3, Wp, Wv);
    alloc_kernel<<<(NN + 255) / 256, 256>>>(bp, out);
    int fl_threads = EPT_T + NFP;
    fill_kernel<<<(fl_threads + 255) / 256, 256>>>(src, dst, features);

    dim3 ggrid((NN + MT - 1) / MT, 2);  // 63 x 2 = 126 CTAs

    // layer 1 (K=128)
    aggregate_kernel<1><<<1250, 256>>>(xh, agg16, 128);
    gemm_mma<<<ggrid, 256>>>(agg16, whi, wlo, b1, xh, 128, 0);
    // layer 2 (K=256): fused exact layer-3 shortcut (y', V partials)
    aggregate_kernel<2><<<1250, 256>>>(xh, agg16, 256);
    gemm_mma<<<ggrid, 256>>>(agg16, whi + 32768, wlo + 32768, b2, xh, 256, 2);
    // PI scalar aggregation + V finalize
    pi_kernel<<<1250, 256>>>(bv, out);
}

// round 16
// speedup vs baseline: 1.6987x; 1.0978x over previous
#include <cuda_runtime.h>
#include <cuda_fp16.h>
#include <cstdint>

#define NN 10000
#define NE 320000
#define F_HID 256
#define EPT_T (NE / 4)   // 80000 edge-threads (4 edges each)

// ---------------- scratch (device globals; no allocation allowed) ----------------
__device__ int   g_deg[NN];
__device__ int   g_incnt[NN];
__device__ int   g_roff[NN];
__device__ int   g_rend[NN];
__device__ int   g_rank[NE];
__device__ int   g_total;
__device__ float g_inv[NN];
__device__ int   g_csr[NE];                                   // src only (premultiplied msgs)
__device__ float g_y[NN];                                     // y'[s] = (x2[s].u) * inv[s]
__device__ float g_u[256];                                    // W3 . Wp
__device__ float g_t[256];                                    // W3 . Wv
__device__ __align__(16) __half g_x16[NN * F_HID];            // premultiplied fp16 gather operand
__device__ __align__(16) __half g_agg16[NN * F_HID];          // agg output = GEMM A operand
__device__ __align__(16) __half g_whi[256 * 256 * 2];         // fp16 hi of W1,W2
__device__ __align__(16) __half g_wlo[256 * 256 * 2];         // fp16 lo of W1,W2
__device__ float g_vsum;
__device__ float g_dotp;   // b3 . Wp
__device__ float g_dotv;   // b3 . Wv

// ---------------- helpers ----------------
__device__ __forceinline__ void ldsm4(uint32_t* r, uint32_t addr) {
    asm volatile("ldmatrix.sync.aligned.m8n8.x4.shared.b16 {%0,%1,%2,%3}, [%4];"
                 : "=r"(r[0]), "=r"(r[1]), "=r"(r[2]), "=r"(r[3]) : "r"(addr));
}
__device__ __forceinline__ void ldsm4t(uint32_t* r, uint32_t addr) {
    asm volatile("ldmatrix.sync.aligned.m8n8.x4.trans.shared.b16 {%0,%1,%2,%3}, [%4];"
                 : "=r"(r[0]), "=r"(r[1]), "=r"(r[2]), "=r"(r[3]) : "r"(addr));
}
__device__ __forceinline__ void mma16816f(float* c, const uint32_t* a, const uint32_t* b) {
    asm volatile(
        "mma.sync.aligned.m16n8k16.row.col.f32.f16.f16.f32 "
        "{%0,%1,%2,%3}, {%4,%5,%6,%7}, {%8,%9}, {%0,%1,%2,%3};"
        : "+f"(c[0]), "+f"(c[1]), "+f"(c[2]), "+f"(c[3])
        : "r"(a[0]), "r"(a[1]), "r"(a[2]), "r"(a[3]), "r"(b[0]), "r"(b[1]));
}
__device__ __forceinline__ uint32_t hadd2u(uint32_t a, uint32_t b) {
    __half2 r = __hadd2(*reinterpret_cast<__half2*>(&a), *reinterpret_cast<__half2*>(&b));
    return *reinterpret_cast<uint32_t*>(&r);
}
__device__ __forceinline__ void acc2(float& a0, float& a1, uint32_t w) {
    float2 f = __half22float2(*reinterpret_cast<__half2*>(&w));
    a0 += f.x; a1 += f.y;
}

// ---------------- count (4 edges/thread) + W hi/lo conversion + u/t matvec + head dots ----------------
// relies on g_deg/g_incnt zero at entry (loader-zeroed; alloc_kernel re-zeros each run)
#define NFP (NN * 128 / 2)          // 640000 feature pairs
#define W1P (128 * 256 / 2)         // 16384
#define W2P (256 * 256 / 2)         // 32768
#define WCONV (W1P + W2P)           // 49152 (W1 + W2)
#define UT_BASE (EPT_T + WCONV)     // 129152 (warp-aligned)
#define CC_TOTAL (UT_BASE + 8192)
__global__ void count_conv_kernel(const int* __restrict__ src, const int* __restrict__ dst,
                                  const float* __restrict__ W1, const float* __restrict__ W2,
                                  const float* __restrict__ W3, const float* __restrict__ b3,
                                  const float* __restrict__ Wp, const float* __restrict__ Wv) {
    int t = blockIdx.x * blockDim.x + threadIdx.x;
    if (t < EPT_T) {
        int s0 = src[t],             d0 = dst[t];
        int s1 = src[t + EPT_T],     d1 = dst[t + EPT_T];
        int s2 = src[t + 2 * EPT_T], d2 = dst[t + 2 * EPT_T];
        int s3 = src[t + 3 * EPT_T], d3 = dst[t + 3 * EPT_T];
        atomicAdd(&g_deg[s0], 1);
        atomicAdd(&g_deg[s1], 1);
        atomicAdd(&g_deg[s2], 1);
        atomicAdd(&g_deg[s3], 1);
        g_rank[t]             = atomicAdd(&g_incnt[d0], 1);
        g_rank[t + EPT_T]     = atomicAdd(&g_incnt[d1], 1);
        g_rank[t + 2 * EPT_T] = atomicAdd(&g_incnt[d2], 1);
        g_rank[t + 3 * EPT_T] = atomicAdd(&g_incnt[d3], 1);
    } else if (t < UT_BASE) {
        int u = t - EPT_T;
        const float* Wsrc;
        int off;
        if (u < W1P) { Wsrc = W1; off = 0; }
        else { Wsrc = W2; off = 32768; u -= W1P; }
        float2 v = *(const float2*)(Wsrc + 2 * u);
        __half2 h = __floats2half2_rn(v.x, v.y);
        float hx = __half2float(__low2half(h));
        float hy = __half2float(__high2half(h));
        __half2 l = __floats2half2_rn(v.x - hx, v.y - hy);
        *(uint32_t*)((char*)g_whi + 2 * (off + 2 * u)) = *reinterpret_cast<uint32_t*>(&h);
        *(uint32_t*)((char*)g_wlo + 2 * (off + 2 * u)) = *reinterpret_cast<uint32_t*>(&l);
    } else if (t < CC_TOTAL) {
        // u/t matvec: warp w computes u[w] = W3[w].Wp, t[w] = W3[w].Wv (fp32 exact)
        int w = (t - UT_BASE) >> 5;
        int ln = t & 31;
        float su = 0.f, st = 0.f;
        #pragma unroll
        for (int c = ln; c < 256; c += 32) {
            float w3 = W3[w * 256 + c];
            su += w3 * Wp[c];
            st += w3 * Wv[c];
        }
        #pragma unroll
        for (int o = 16; o > 0; o >>= 1) {
            su += __shfl_xor_sync(0xffffffffu, su, o);
            st += __shfl_xor_sync(0xffffffffu, st, o);
        }
        if (ln == 0) { g_u[w] = su; g_t[w] = st; }
    }
    if (blockIdx.x == 0) {
        __shared__ float sp[8], sv[8];
        int tt = threadIdx.x;  // 256
        float pd = b3[tt] * Wp[tt];
        float pv = b3[tt] * Wv[tt];
        #pragma unroll
        for (int o = 16; o > 0; o >>= 1) {
            pd += __shfl_xor_sync(0xffffffffu, pd, o);
            pv += __shfl_xor_sync(0xffffffffu, pv, o);
        }
        if ((tt & 31) == 0) { sp[tt >> 5] = pd; sv[tt >> 5] = pv; }
        __syncthreads();
        if (tt == 0) {
            float a = 0.f, b = 0.f;
            #pragma unroll
            for (int w = 0; w < 8; w++) { a += sp[w]; b += sv[w]; }
            g_dotp = a; g_dotv = b;
        }
    }
}

// order-free CSR bucket allocation + PI const init + y/vsum zero + counter re-zero
__global__ void alloc_kernel(const float* __restrict__ bp, float* __restrict__ out) {
    int i = blockIdx.x * blockDim.x + threadIdx.x;
    if (i < NN) {
        int c = g_incnt[i];
        int base = atomicAdd(&g_total, c);
        g_roff[i] = base;
        g_rend[i] = base + c;
        int d = g_deg[i];
        g_inv[i] = (d > 0) ? 1.0f / (float)d : 0.0f;
        out[i] = bp[0] + g_dotp;   // PI constant: b3.Wp + bp
        g_y[i] = 0.f;
        g_incnt[i] = 0;
        g_deg[i] = 0;
        if (i == 0) g_vsum = 0.f;
    }
}

// fill CSR (4 edges/thread) + premultiplied fp16 feature conversion (needs g_inv)
__global__ void fill_kernel(const int* __restrict__ src, const int* __restrict__ dst,
                            const float* __restrict__ X) {
    int t = blockIdx.x * blockDim.x + threadIdx.x;
    if (t < EPT_T) {
        int e[4] = { t, t + EPT_T, t + 2 * EPT_T, t + 3 * EPT_T };
        int s[4], d[4], r[4];
        #pragma unroll
        for (int q = 0; q < 4; q++) { s[q] = src[e[q]]; d[q] = dst[e[q]]; r[q] = g_rank[e[q]]; }
        int p[4];
        #pragma unroll
        for (int q = 0; q < 4; q++) p[q] = g_roff[d[q]] + r[q];
        #pragma unroll
        for (int q = 0; q < 4; q++) g_csr[p[q]] = s[q];
    } else if (t - EPT_T < NFP) {
        int c = t - EPT_T;               // feature pair index
        int node = c >> 6;               // 64 pairs per node (F=128)
        float iv = g_inv[node];
        float2 v = *(const float2*)(X + 2 * c);
        __half2 h = __floats2half2_rn(v.x * iv, v.y * iv);
        *(uint32_t*)((char*)g_x16 + 4 * c) = *reinterpret_cast<uint32_t*>(&h);
    }
}

// ---------------- edge aggregation: unweighted sum of premultiplied fp16 rows ----------------
// One-level HADD2 pairing of edges (one fp16 rounding at half-scale), then fp32 accumulate.
template <int CHUNKS>  // 1: F=128 (uint2/lane, 8-edge batches), 2: F=256 (uint4/lane, 4-edge batches)
__global__ void aggregate_kernel(const __half* __restrict__ X,
                                 __half* __restrict__ Y, int F) {
    int gw    = (blockIdx.x * blockDim.x + threadIdx.x) >> 5;
    int lane  = threadIdx.x & 31;
    int nwrp  = (gridDim.x * blockDim.x) >> 5;
    const int ROWB = F * 2;
    const char* Xb = (const char*)X + lane * (CHUNKS == 1 ? 8 : 16);
    for (int n = gw; n < NN; n += nwrp) {
        int s0 = g_roff[n], s1 = g_rend[n];
        float4 acc0 = make_float4(0.f, 0.f, 0.f, 0.f);
        float4 acc1 = make_float4(0.f, 0.f, 0.f, 0.f);
        for (int e0 = s0; e0 < s1; e0 += 32) {
            uint32_t offl = 0;
            if (e0 + lane < s1) offl = (uint32_t)g_csr[e0 + lane] * ROWB;
            int cnt = min(32, s1 - e0);
            int j = 0;
            if (CHUNKS == 1) {
                for (; j + 8 <= cnt; j += 8) {
                    uint32_t of[8];
                    #pragma unroll
                    for (int q = 0; q < 8; q++)
                        of[q] = __shfl_sync(0xffffffffu, offl, j + q);
                    uint2 v[8];
                    #pragma unroll
                    for (int q = 0; q < 8; q++)
                        v[q] = *(const uint2*)(Xb + of[q]);
                    // pair in fp16 (4 pairs), then convert+accumulate in fp32
                    #pragma unroll
                    for (int q = 0; q < 4; q++) {
                        uint32_t px = hadd2u(v[2 * q].x, v[2 * q + 1].x);
                        uint32_t py = hadd2u(v[2 * q].y, v[2 * q + 1].y);
                        acc2(acc0.x, acc0.y, px);
                        acc2(acc0.z, acc0.w, py);
                    }
                }
                for (; j < cnt; j++) {
                    uint32_t of = __shfl_sync(0xffffffffu, offl, j);
                    uint2 v = *(const uint2*)(Xb + of);
                    acc2(acc0.x, acc0.y, v.x);
                    acc2(acc0.z, acc0.w, v.y);
                }
            } else {
                for (; j + 4 <= cnt; j += 4) {
                    uint32_t of[4];
                    #pragma unroll
                    for (int q = 0; q < 4; q++)
                        of[q] = __shfl_sync(0xffffffffu, offl, j + q);
                    uint4 v[4];
                    #pragma unroll
                    for (int q = 0; q < 4; q++)
                        v[q] = *(const uint4*)(Xb + of[q]);
                    // pair in fp16 (2 pairs), then convert+accumulate in fp32
                    #pragma unroll
                    for (int q = 0; q < 2; q++) {
                        uint32_t px = hadd2u(v[2 * q].x, v[2 * q + 1].x);
                        uint32_t py = hadd2u(v[2 * q].y, v[2 * q + 1].y);
                        uint32_t pz = hadd2u(v[2 * q].z, v[2 * q + 1].z);
                        uint32_t pw = hadd2u(v[2 * q].w, v[2 * q + 1].w);
                        acc2(acc0.x, acc0.y, px);
                        acc2(acc0.z, acc0.w, py);
                        acc2(acc1.x, acc1.y, pz);
                        acc2(acc1.z, acc1.w, pw);
                    }
                }
                for (; j < cnt; j++) {
                    uint32_t of = __shfl_sync(0xffffffffu, offl, j);
                    uint4 v = *(const uint4*)(Xb + of);
                    acc2(acc0.x, acc0.y, v.x);
                    acc2(acc0.z, acc0.w, v.y);
                    acc2(acc1.x, acc1.y, v.z);
                    acc2(acc1.z, acc1.w, v.w);
                }
            }
        }
        __half2 p0 = __floats2half2_rn(acc0.x, acc0.y);
        __half2 p1 = __floats2half2_rn(acc0.z, acc0.w);
        if (CHUNKS == 1) {
            ((uint2*)(Y + (size_t)n * F))[lane] =
                make_uint2(*reinterpret_cast<uint32_t*>(&p0), *reinterpret_cast<uint32_t*>(&p1));
        } else {
            __half2 p2 = __floats2half2_rn(acc1.x, acc1.y);
            __half2 p3 = __floats2half2_rn(acc1.z, acc1.w);
            ((uint4*)(Y + (size_t)n * F))[lane] =
                make_uint4(*reinterpret_cast<uint32_t*>(&p0), *reinterpret_cast<uint32_t*>(&p1),
                           *reinterpret_cast<uint32_t*>(&p2), *reinterpret_cast<uint32_t*>(&p3));
        }
    }
}

// ---------------- GEMM via mma.sync fp16 with W hi/lo (2 products) ----------------
// CTA tile 160x128, 8 warps (2m x 4n), warp tile 80x32, BK=32 -> 126 CTAs
// mode 0: layer 1 — relu, premultiply by inv_deg, write fp16 gather operand
// mode 2: layer 2 — relu in registers, emit y'[row] = (x2.u)*inv and V partial (x2.t, deg>0)
#define MT 160
#define AS_STRIDE 40
#define BS_STRIDE 136
__global__ void __launch_bounds__(256)
gemm_mma(const __half* __restrict__ A, const __half* __restrict__ Whi,
         const __half* __restrict__ Wlo, const float* __restrict__ bias,
         __half* __restrict__ XH, int K, int mode) {
    __shared__ __align__(16) __half sA[MT * AS_STRIDE];
    __shared__ __align__(16) __half sBhi[32 * BS_STRIDE];
    __shared__ __align__(16) __half sBlo[32 * BS_STRIDE];
    __shared__ float sbias[128];
    __shared__ float spi[MT];
    __shared__ float svred[8];

    int tid = threadIdx.x;
    int m0 = blockIdx.x * MT, n0 = blockIdx.y * 128;
    if (tid < 128) sbias[tid] = bias[n0 + tid];
    int wid = tid >> 5, lane = tid & 31;
    int wm = (wid & 1) * 80, wn = (wid >> 1) * 32;

    float acc[5][4][4];
    #pragma unroll
    for (int i = 0; i < 5; i++)
        #pragma unroll
        for (int j = 0; j < 4; j++)
            #pragma unroll
            for (int q = 0; q < 4; q++) acc[i][j][q] = 0.f;

    const uint4 z4 = make_uint4(0, 0, 0, 0);

    for (int kc = 0; kc < K; kc += 32) {
        #pragma unroll
        for (int idx = tid; idx < MT * 4; idx += 256) {
            int row = idx >> 2, c16 = idx & 3;
            int gr = m0 + row;
            uint4 vh = z4;
            if (gr < NN)
                vh = *(const uint4*)(A + (size_t)gr * K + kc + c16 * 8);
            *(uint4*)(sA + row * AS_STRIDE + c16 * 8) = vh;
        }
        #pragma unroll
        for (int idx = tid; idx < 512; idx += 256) {
            int row = idx >> 4, c16 = idx & 15;
            size_t goff = (size_t)(kc + row) * 256 + n0 + c16 * 8;
            *(uint4*)(sBhi + row * BS_STRIDE + c16 * 8) = *(const uint4*)(Whi + goff);
            *(uint4*)(sBlo + row * BS_STRIDE + c16 * 8) = *(const uint4*)(Wlo + goff);
        }
        __syncthreads();

        #pragma unroll
        for (int k16 = 0; k16 < 2; k16++) {
            uint32_t ah[5][4], bh[4][2], bl[4][2];
            #pragma unroll
            for (int mt = 0; mt < 5; mt++) {
                int row = wm + mt * 16 + (lane & 15);
                int col = k16 * 16 + (lane >> 4) * 8;
                uint32_t ad = (uint32_t)__cvta_generic_to_shared(sA + row * AS_STRIDE + col);
                ldsm4(ah[mt], ad);
            }
            #pragma unroll
            for (int nt2 = 0; nt2 < 2; nt2++) {
                int row = k16 * 16 + (lane & 15);
                int col = wn + nt2 * 16 + ((lane >> 4) & 1) * 8;
                uint32_t t[4];
                uint32_t ad = (uint32_t)__cvta_generic_to_shared(sBhi + row * BS_STRIDE + col);
                ldsm4t(t, ad);
                bh[nt2 * 2][0] = t[0]; bh[nt2 * 2][1] = t[1];
                bh[nt2 * 2 + 1][0] = t[2]; bh[nt2 * 2 + 1][1] = t[3];
                ad = (uint32_t)__cvta_generic_to_shared(sBlo + row * BS_STRIDE + col);
                ldsm4t(t, ad);
                bl[nt2 * 2][0] = t[0]; bl[nt2 * 2][1] = t[1];
                bl[nt2 * 2 + 1][0] = t[2]; bl[nt2 * 2 + 1][1] = t[3];
            }
            #pragma unroll
            for (int mt = 0; mt < 5; mt++)
                #pragma unroll
                for (int nt = 0; nt < 4; nt++) {
                    mma16816f(acc[mt][nt], ah[mt], bh[nt]);
                    mma16816f(acc[mt][nt], ah[mt], bl[nt]);
                }
        }
        __syncthreads();
    }

    if (mode == 0) {
        #pragma unroll
        for (int mt = 0; mt < 5; mt++) {
            int r0 = m0 + wm + mt * 16 + (lane >> 2);
            int r1 = r0 + 8;
            float i0 = (r0 < NN) ? g_inv[r0] : 0.f;
            float i1 = (r1 < NN) ? g_inv[r1] : 0.f;
            #pragma unroll
            for (int nt = 0; nt < 4; nt++) {
                int cl = wn + nt * 8 + (lane & 3) * 2;
                float b0 = sbias[cl], b1 = sbias[cl + 1];
                float v0 = fmaxf(acc[mt][nt][0] + b0, 0.f) * i0;
                float v1 = fmaxf(acc[mt][nt][1] + b1, 0.f) * i0;
                float v2 = fmaxf(acc[mt][nt][2] + b0, 0.f) * i1;
                float v3 = fmaxf(acc[mt][nt][3] + b1, 0.f) * i1;
                if (r0 < NN) {
                    __half2 h = __floats2half2_rn(v0, v1);
                    *(uint32_t*)(XH + (size_t)r0 * 256 + n0 + cl) = *reinterpret_cast<uint32_t*>(&h);
                }
                if (r1 < NN) {
                    __half2 h = __floats2half2_rn(v2, v3);
                    *(uint32_t*)(XH + (size_t)r1 * 256 + n0 + cl) = *reinterpret_cast<uint32_t*>(&h);
                }
            }
        }
    } else {
        // layer-2 fused: y' partial = relu(x2).u ; V partial = relu(x2).t (deg>0)
        float wu[8], wt[8];
        #pragma unroll
        for (int nt = 0; nt < 4; nt++) {
            int cg = n0 + wn + nt * 8 + (lane & 3) * 2;
            wu[nt * 2] = g_u[cg]; wu[nt * 2 + 1] = g_u[cg + 1];
            wt[nt * 2] = g_t[cg]; wt[nt * 2 + 1] = g_t[cg + 1];
        }
        for (int i = tid; i < MT; i += 256) spi[i] = 0.f;
        __syncthreads();
        float vth = 0.f;
        #pragma unroll
        for (int mt = 0; mt < 5; mt++) {
            int r0 = m0 + wm + mt * 16 + (lane >> 2);
            int r1 = r0 + 8;
            float i0 = (r0 < NN) ? g_inv[r0] : 0.f;
            float i1 = (r1 < NN) ? g_inv[r1] : 0.f;
            float p0 = 0.f, p1 = 0.f, q0 = 0.f, q1 = 0.f;
            #pragma unroll
            for (int nt = 0; nt < 4; nt++) {
                int cl = wn + nt * 8 + (lane & 3) * 2;
                float b0 = sbias[cl], b1 = sbias[cl + 1];
                float v0 = fmaxf(acc[mt][nt][0] + b0, 0.f);
                float v1 = fmaxf(acc[mt][nt][1] + b1, 0.f);
                float v2 = fmaxf(acc[mt][nt][2] + b0, 0.f);
                float v3 = fmaxf(acc[mt][nt][3] + b1, 0.f);
                p0 += v0 * wu[nt * 2] + v1 * wu[nt * 2 + 1];
                p1 += v2 * wu[nt * 2] + v3 * wu[nt * 2 + 1];
                q0 += v0 * wt[nt * 2] + v1 * wt[nt * 2 + 1];
                q1 += v2 * wt[nt * 2] + v3 * wt[nt * 2 + 1];
            }
            #pragma unroll
            for (int o = 1; o <= 2; o <<= 1) {
                p0 += __shfl_xor_sync(0xffffffffu, p0, o);
                p1 += __shfl_xor_sync(0xffffffffu, p1, o);
                q0 += __shfl_xor_sync(0xffffffffu, q0, o);
                q1 += __shfl_xor_sync(0xffffffffu, q1, o);
            }
            if ((lane & 3) == 0) {
                int lr = wm + mt * 16 + (lane >> 2);
                atomicAdd(&spi[lr], p0);
                atomicAdd(&spi[lr + 8], p1);
                vth += (i0 > 0.f ? q0 : 0.f) + (i1 > 0.f ? q1 : 0.f);
            }
        }
        #pragma unroll
        for (int o = 16; o > 0; o >>= 1) vth += __shfl_xor_sync(0xffffffffu, vth, o);
        if (lane == 0) svred[wid] = vth;
        __syncthreads();
        for (int i = tid; i < MT; i += 256) {
            int gr = m0 + i;
            if (gr < NN) atomicAdd(&g_y[gr], spi[i] * g_inv[gr]);
        }
        if (tid == 0) {
            float s = 0.f;
            #pragma unroll
            for (int w = 0; w < 8; w++) s += svred[w];
            atomicAdd(&g_vsum, s);
        }
    }
}

// ---------------- PI: scalar aggregation of y' over in-edges + final V write ----------------
__global__ void pi_kernel(const float* __restrict__ bv, float* __restrict__ out) {
    int gw   = (blockIdx.x * blockDim.x + threadIdx.x) >> 5;
    int lane = threadIdx.x & 31;
    int nwrp = (gridDim.x * blockDim.x) >> 5;
    for (int n = gw; n < NN; n += nwrp) {
        int s0 = g_roff[n], s1 = g_rend[n];
        float sum = 0.f;
        for (int e = s0 + lane; e < s1; e += 32)
            sum += g_y[g_csr[e]];
        #pragma unroll
        for (int o = 16; o > 0; o >>= 1)
            sum += __shfl_xor_sync(0xffffffffu, sum, o);
        if (lane == 0) out[n] += sum;
    }
    if (blockIdx.x == 0 && threadIdx.x == 0) {
        out[NN] = g_vsum * (1.0f / (float)NN) + g_dotv + bv[0];
        g_total = 0;   // restore invariant for next run
    }
}

// ---------------- launch ----------------
extern "C" void kernel_launch(void* const* d_in, const int* in_sizes, int n_in,
                              void* d_out, int out_size) {
    const float* features = (const float*)d_in[0];
    const int*   src      = (const int*)d_in[1];
    const int*   dst      = (const int*)d_in[2];
    const float* W1 = (const float*)d_in[3];
    const float* b1 = (const float*)d_in[4];
    const float* W2 = (const float*)d_in[5];
    const float* b2 = (const float*)d_in[6];
    const float* W3 = (const float*)d_in[7];
    const float* b3 = (const float*)d_in[8];
    const float* Wp = (const float*)d_in[9];
    const float* bp = (const float*)d_in[10];
    const float* Wv = (const float*)d_in[11];
    const float* bv = (const float*)d_in[12];
    float* out = (float*)d_out;

    void *pXH_, *pAgg_, *pWhi_, *pWlo_;
    cudaGetSymbolAddress(&pXH_, g_x16);
    cudaGetSymbolAddress(&pAgg_, g_agg16);
    cudaGetSymbolAddress(&pWhi_, g_whi);
    cudaGetSymbolAddress(&pWlo_, g_wlo);
    __half* xh = (__half*)pXH_;
    __half* agg16 = (__half*)pAgg_;
    __half* whi = (__half*)pWhi_;
    __half* wlo = (__half*)pWlo_;

    // preprocessing
    count_conv_kernel<<<(CC_TOTAL + 255) / 256, 256>>>(src, dst, W1, W2, W3, b3, Wp, Wv);
    alloc_kernel<<<(NN + 255) / 256, 256>>>(bp, out);
    int fl_threads = EPT_T + NFP;
    fill_kernel<<<(fl_threads + 255) / 256, 256>>>(src, dst, features);

    dim3 ggrid((NN + MT - 1) / MT, 2);  // 63 x 2 = 126 CTAs

    // layer 1 (K=128)
    aggregate_kernel<1><<<1250, 256>>>(xh, agg16, 128);
    gemm_mma<<<ggrid, 256>>>(agg16, whi, wlo, b1, xh, 128, 0);
    // layer 2 (K=256): fused exact layer-3 shortcut (y', V partials)
    aggregate_kernel<2><<<1250, 256>>>(xh, agg16, 256);
    gemm_mma<<<ggrid, 256>>>(agg16, whi + 32768, wlo + 32768, b2, xh, 256, 2);
    // PI scalar aggregation + V finalize
    pi_kernel<<<1250, 256>>>(bv, out);
}

// round 17
// speedup vs baseline: 1.7456x; 1.0276x over previous
#include <cuda_runtime.h>
#include <cuda_fp16.h>
#include <cstdint>

#define NN 10000
#define NE 320000
#define F_HID 256
#define EPT_T (NE / 4)   // 80000 edge-threads (4 edges each)

// ---------------- scratch (device globals; no allocation allowed) ----------------
__device__ int   g_deg[NN];
__device__ int   g_incnt[NN];
__device__ int   g_roff[NN];
__device__ int   g_rend[NN];
__device__ int   g_rank[NE];
__device__ int   g_total;
__device__ float g_inv[NN];
__device__ int   g_csr[NE];                                   // src only (premultiplied msgs)
__device__ float g_y[NN];                                     // y'[s] = (x2[s].u) * inv[s]
__device__ float g_u[256];                                    // W3 . Wp
__device__ float g_t[256];                                    // W3 . Wv
__device__ __align__(16) __half g_x16[NN * F_HID];            // premultiplied fp16 gather operand
__device__ __align__(16) __half g_agg16[NN * F_HID];          // agg output = GEMM A operand
__device__ __align__(16) __half g_whi[256 * 256 * 2];         // fp16 hi of W1,W2
__device__ __align__(16) __half g_wlo[256 * 256 * 2];         // fp16 lo of W1,W2
__device__ float g_vsum;
__device__ float g_dotp;   // b3 . Wp
__device__ float g_dotv;   // b3 . Wv

// ---------------- helpers ----------------
__device__ __forceinline__ void ldsm4(uint32_t* r, uint32_t addr) {
    asm volatile("ldmatrix.sync.aligned.m8n8.x4.shared.b16 {%0,%1,%2,%3}, [%4];"
                 : "=r"(r[0]), "=r"(r[1]), "=r"(r[2]), "=r"(r[3]) : "r"(addr));
}
__device__ __forceinline__ void ldsm4t(uint32_t* r, uint32_t addr) {
    asm volatile("ldmatrix.sync.aligned.m8n8.x4.trans.shared.b16 {%0,%1,%2,%3}, [%4];"
                 : "=r"(r[0]), "=r"(r[1]), "=r"(r[2]), "=r"(r[3]) : "r"(addr));
}
__device__ __forceinline__ void mma16816f(float* c, const uint32_t* a, const uint32_t* b) {
    asm volatile(
        "mma.sync.aligned.m16n8k16.row.col.f32.f16.f16.f32 "
        "{%0,%1,%2,%3}, {%4,%5,%6,%7}, {%8,%9}, {%0,%1,%2,%3};"
        : "+f"(c[0]), "+f"(c[1]), "+f"(c[2]), "+f"(c[3])
        : "r"(a[0]), "r"(a[1]), "r"(a[2]), "r"(a[3]), "r"(b[0]), "r"(b[1]));
}
__device__ __forceinline__ uint32_t hadd2u(uint32_t a, uint32_t b) {
    __half2 r = __hadd2(*reinterpret_cast<__half2*>(&a), *reinterpret_cast<__half2*>(&b));
    return *reinterpret_cast<uint32_t*>(&r);
}
__device__ __forceinline__ void acc2(float& a0, float& a1, uint32_t w) {
    float2 f = __half22float2(*reinterpret_cast<__half2*>(&w));
    a0 += f.x; a1 += f.y;
}

// ---------------- count (4 edges/thread) + W hi/lo conversion + u/t matvec + head dots ----------------
// relies on g_deg/g_incnt zero at entry (loader-zeroed; alloc_kernel re-zeros each run)
#define NFP (NN * 128 / 2)          // 640000 feature pairs
#define W1P (128 * 256 / 2)         // 16384
#define W2P (256 * 256 / 2)         // 32768
#define WCONV (W1P + W2P)           // 49152 (W1 + W2)
#define UT_BASE (EPT_T + WCONV)     // 129152 (warp-aligned)
#define CC_TOTAL (UT_BASE + 8192)
__global__ void count_conv_kernel(const int* __restrict__ src, const int* __restrict__ dst,
                                  const float* __restrict__ W1, const float* __restrict__ W2,
                                  const float* __restrict__ W3, const float* __restrict__ b3,
                                  const float* __restrict__ Wp, const float* __restrict__ Wv) {
    int t = blockIdx.x * blockDim.x + threadIdx.x;
    if (t < EPT_T) {
        int s0 = src[t],             d0 = dst[t];
        int s1 = src[t + EPT_T],     d1 = dst[t + EPT_T];
        int s2 = src[t + 2 * EPT_T], d2 = dst[t + 2 * EPT_T];
        int s3 = src[t + 3 * EPT_T], d3 = dst[t + 3 * EPT_T];
        atomicAdd(&g_deg[s0], 1);
        atomicAdd(&g_deg[s1], 1);
        atomicAdd(&g_deg[s2], 1);
        atomicAdd(&g_deg[s3], 1);
        g_rank[t]             = atomicAdd(&g_incnt[d0], 1);
        g_rank[t + EPT_T]     = atomicAdd(&g_incnt[d1], 1);
        g_rank[t + 2 * EPT_T] = atomicAdd(&g_incnt[d2], 1);
        g_rank[t + 3 * EPT_T] = atomicAdd(&g_incnt[d3], 1);
    } else if (t < UT_BASE) {
        int u = t - EPT_T;
        const float* Wsrc;
        int off;
        if (u < W1P) { Wsrc = W1; off = 0; }
        else { Wsrc = W2; off = 32768; u -= W1P; }
        float2 v = *(const float2*)(Wsrc + 2 * u);
        __half2 h = __floats2half2_rn(v.x, v.y);
        float hx = __half2float(__low2half(h));
        float hy = __half2float(__high2half(h));
        __half2 l = __floats2half2_rn(v.x - hx, v.y - hy);
        *(uint32_t*)((char*)g_whi + 2 * (off + 2 * u)) = *reinterpret_cast<uint32_t*>(&h);
        *(uint32_t*)((char*)g_wlo + 2 * (off + 2 * u)) = *reinterpret_cast<uint32_t*>(&l);
    } else if (t < CC_TOTAL) {
        // u/t matvec: warp w computes u[w] = W3[w].Wp, t[w] = W3[w].Wv (fp32 exact)
        int w = (t - UT_BASE) >> 5;
        int ln = t & 31;
        float su = 0.f, st = 0.f;
        #pragma unroll
        for (int c = ln; c < 256; c += 32) {
            float w3 = W3[w * 256 + c];
            su += w3 * Wp[c];
            st += w3 * Wv[c];
        }
        #pragma unroll
        for (int o = 16; o > 0; o >>= 1) {
            su += __shfl_xor_sync(0xffffffffu, su, o);
            st += __shfl_xor_sync(0xffffffffu, st, o);
        }
        if (ln == 0) { g_u[w] = su; g_t[w] = st; }
    }
    if (blockIdx.x == 0) {
        __shared__ float sp[8], sv[8];
        int tt = threadIdx.x;  // 256
        float pd = b3[tt] * Wp[tt];
        float pv = b3[tt] * Wv[tt];
        #pragma unroll
        for (int o = 16; o > 0; o >>= 1) {
            pd += __shfl_xor_sync(0xffffffffu, pd, o);
            pv += __shfl_xor_sync(0xffffffffu, pv, o);
        }
        if ((tt & 31) == 0) { sp[tt >> 5] = pd; sv[tt >> 5] = pv; }
        __syncthreads();
        if (tt == 0) {
            float a = 0.f, b = 0.f;
            #pragma unroll
            for (int w = 0; w < 8; w++) { a += sp[w]; b += sv[w]; }
            g_dotp = a; g_dotv = b;
        }
    }
}

// order-free CSR bucket allocation + PI const init + y/vsum zero + counter re-zero
__global__ void alloc_kernel(const float* __restrict__ bp, float* __restrict__ out) {
    int i = blockIdx.x * blockDim.x + threadIdx.x;
    if (i < NN) {
        int c = g_incnt[i];
        int base = atomicAdd(&g_total, c);
        g_roff[i] = base;
        g_rend[i] = base + c;
        int d = g_deg[i];
        g_inv[i] = (d > 0) ? 1.0f / (float)d : 0.0f;
        out[i] = bp[0] + g_dotp;   // PI constant: b3.Wp + bp
        g_y[i] = 0.f;
        g_incnt[i] = 0;
        g_deg[i] = 0;
        if (i == 0) g_vsum = 0.f;
    }
}

// fill CSR (4 edges/thread) + premultiplied fp16 feature conversion (needs g_inv)
__global__ void fill_kernel(const int* __restrict__ src, const int* __restrict__ dst,
                            const float* __restrict__ X) {
    int t = blockIdx.x * blockDim.x + threadIdx.x;
    if (t < EPT_T) {
        int e[4] = { t, t + EPT_T, t + 2 * EPT_T, t + 3 * EPT_T };
        int s[4], d[4], r[4];
        #pragma unroll
        for (int q = 0; q < 4; q++) { s[q] = src[e[q]]; d[q] = dst[e[q]]; r[q] = g_rank[e[q]]; }
        int p[4];
        #pragma unroll
        for (int q = 0; q < 4; q++) p[q] = g_roff[d[q]] + r[q];
        #pragma unroll
        for (int q = 0; q < 4; q++) g_csr[p[q]] = s[q];
    } else if (t - EPT_T < NFP) {
        int c = t - EPT_T;               // feature pair index
        int node = c >> 6;               // 64 pairs per node (F=128)
        float iv = g_inv[node];
        float2 v = *(const float2*)(X + 2 * c);
        __half2 h = __floats2half2_rn(v.x * iv, v.y * iv);
        *(uint32_t*)((char*)g_x16 + 4 * c) = *reinterpret_cast<uint32_t*>(&h);
    }
}

// ---------------- edge aggregation: unweighted sum of premultiplied fp16 rows ----------------
// Two-level HADD2 tree (sum 4 edges in fp16), then fp32 accumulate.
template <int CHUNKS>  // 1: F=128 (uint2/lane, 8-edge batches), 2: F=256 (uint4/lane, 4-edge batches)
__global__ void aggregate_kernel(const __half* __restrict__ X,
                                 __half* __restrict__ Y, int F) {
    int gw    = (blockIdx.x * blockDim.x + threadIdx.x) >> 5;
    int lane  = threadIdx.x & 31;
    int nwrp  = (gridDim.x * blockDim.x) >> 5;
    const int ROWB = F * 2;
    const char* Xb = (const char*)X + lane * (CHUNKS == 1 ? 8 : 16);
    for (int n = gw; n < NN; n += nwrp) {
        int s0 = g_roff[n], s1 = g_rend[n];
        float4 acc0 = make_float4(0.f, 0.f, 0.f, 0.f);
        float4 acc1 = make_float4(0.f, 0.f, 0.f, 0.f);
        for (int e0 = s0; e0 < s1; e0 += 32) {
            uint32_t offl = 0;
            if (e0 + lane < s1) offl = (uint32_t)g_csr[e0 + lane] * ROWB;
            int cnt = min(32, s1 - e0);
            int j = 0;
            if (CHUNKS == 1) {
                for (; j + 8 <= cnt; j += 8) {
                    uint32_t of[8];
                    #pragma unroll
                    for (int q = 0; q < 8; q++)
                        of[q] = __shfl_sync(0xffffffffu, offl, j + q);
                    uint2 v[8];
                    #pragma unroll
                    for (int q = 0; q < 8; q++)
                        v[q] = *(const uint2*)(Xb + of[q]);
                    // level 1: 4 pairs per component
                    uint32_t px[4], py[4];
                    #pragma unroll
                    for (int q = 0; q < 4; q++) {
                        px[q] = hadd2u(v[2 * q].x, v[2 * q + 1].x);
                        py[q] = hadd2u(v[2 * q].y, v[2 * q + 1].y);
                    }
                    // level 2: 2 quads per component, then fp32 accumulate
                    acc2(acc0.x, acc0.y, hadd2u(px[0], px[1]));
                    acc2(acc0.x, acc0.y, hadd2u(px[2], px[3]));
                    acc2(acc0.z, acc0.w, hadd2u(py[0], py[1]));
                    acc2(acc0.z, acc0.w, hadd2u(py[2], py[3]));
                }
                for (; j < cnt; j++) {
                    uint32_t of = __shfl_sync(0xffffffffu, offl, j);
                    uint2 v = *(const uint2*)(Xb + of);
                    acc2(acc0.x, acc0.y, v.x);
                    acc2(acc0.z, acc0.w, v.y);
                }
            } else {
                for (; j + 4 <= cnt; j += 4) {
                    uint32_t of[4];
                    #pragma unroll
                    for (int q = 0; q < 4; q++)
                        of[q] = __shfl_sync(0xffffffffu, offl, j + q);
                    uint4 v[4];
                    #pragma unroll
                    for (int q = 0; q < 4; q++)
                        v[q] = *(const uint4*)(Xb + of[q]);
                    // level 1 + level 2 per component (sum of all 4 edges in fp16)
                    uint32_t sx = hadd2u(hadd2u(v[0].x, v[1].x), hadd2u(v[2].x, v[3].x));
                    uint32_t sy = hadd2u(hadd2u(v[0].y, v[1].y), hadd2u(v[2].y, v[3].y));
                    uint32_t sz = hadd2u(hadd2u(v[0].z, v[1].z), hadd2u(v[2].z, v[3].z));
                    uint32_t sw = hadd2u(hadd2u(v[0].w, v[1].w), hadd2u(v[2].w, v[3].w));
                    acc2(acc0.x, acc0.y, sx);
                    acc2(acc0.z, acc0.w, sy);
                    acc2(acc1.x, acc1.y, sz);
                    acc2(acc1.z, acc1.w, sw);
                }
                for (; j < cnt; j++) {
                    uint32_t of = __shfl_sync(0xffffffffu, offl, j);
                    uint4 v = *(const uint4*)(Xb + of);
                    acc2(acc0.x, acc0.y, v.x);
                    acc2(acc0.z, acc0.w, v.y);
                    acc2(acc1.x, acc1.y, v.z);
                    acc2(acc1.z, acc1.w, v.w);
                }
            }
        }
        __half2 p0 = __floats2half2_rn(acc0.x, acc0.y);
        __half2 p1 = __floats2half2_rn(acc0.z, acc0.w);
        if (CHUNKS == 1) {
            ((uint2*)(Y + (size_t)n * F))[lane] =
                make_uint2(*reinterpret_cast<uint32_t*>(&p0), *reinterpret_cast<uint32_t*>(&p1));
        } else {
            __half2 p2 = __floats2half2_rn(acc1.x, acc1.y);
            __half2 p3 = __floats2half2_rn(acc1.z, acc1.w);
            ((uint4*)(Y + (size_t)n * F))[lane] =
                make_uint4(*reinterpret_cast<uint32_t*>(&p0), *reinterpret_cast<uint32_t*>(&p1),
                           *reinterpret_cast<uint32_t*>(&p2), *reinterpret_cast<uint32_t*>(&p3));
        }
    }
}

// ---------------- GEMM via mma.sync fp16 with W hi/lo (2 products) ----------------
// CTA tile 160x128, 8 warps (2m x 4n), warp tile 80x32, BK=32 -> 126 CTAs
// mode 0: layer 1 — relu, premultiply by inv_deg, write fp16 gather operand
// mode 2: layer 2 — relu in registers, emit y'[row] = (x2.u)*inv and V partial (x2.t, deg>0)
#define MT 160
#define AS_STRIDE 40
#define BS_STRIDE 136
__global__ void __launch_bounds__(256)
gemm_mma(const __half* __restrict__ A, const __half* __restrict__ Whi,
         const __half* __restrict__ Wlo, const float* __restrict__ bias,
         __half* __restrict__ XH, int K, int mode) {
    __shared__ __align__(16) __half sA[MT * AS_STRIDE];
    __shared__ __align__(16) __half sBhi[32 * BS_STRIDE];
    __shared__ __align__(16) __half sBlo[32 * BS_STRIDE];
    __shared__ float sbias[128];
    __shared__ float spi[MT];
    __shared__ float svred[8];

    int tid = threadIdx.x;
    int m0 = blockIdx.x * MT, n0 = blockIdx.y * 128;
    if (tid < 128) sbias[tid] = bias[n0 + tid];
    int wid = tid >> 5, lane = tid & 31;
    int wm = (wid & 1) * 80, wn = (wid >> 1) * 32;

    float acc[5][4][4];
    #pragma unroll
    for (int i = 0; i < 5; i++)
        #pragma unroll
        for (int j = 0; j < 4; j++)
            #pragma unroll
            for (int q = 0; q < 4; q++) acc[i][j][q] = 0.f;

    const uint4 z4 = make_uint4(0, 0, 0, 0);

    for (int kc = 0; kc < K; kc += 32) {
        #pragma unroll
        for (int idx = tid; idx < MT * 4; idx += 256) {
            int row = idx >> 2, c16 = idx & 3;
            int gr = m0 + row;
            uint4 vh = z4;
            if (gr < NN)
                vh = *(const uint4*)(A + (size_t)gr * K + kc + c16 * 8);
            *(uint4*)(sA + row * AS_STRIDE + c16 * 8) = vh;
        }
        #pragma unroll
        for (int idx = tid; idx < 512; idx += 256) {
            int row = idx >> 4, c16 = idx & 15;
            size_t goff = (size_t)(kc + row) * 256 + n0 + c16 * 8;
            *(uint4*)(sBhi + row * BS_STRIDE + c16 * 8) = *(const uint4*)(Whi + goff);
            *(uint4*)(sBlo + row * BS_STRIDE + c16 * 8) = *(const uint4*)(Wlo + goff);
        }
        __syncthreads();

        #pragma unroll
        for (int k16 = 0; k16 < 2; k16++) {
            uint32_t ah[5][4], bh[4][2], bl[4][2];
            #pragma unroll
            for (int mt = 0; mt < 5; mt++) {
                int row = wm + mt * 16 + (lane & 15);
                int col = k16 * 16 + (lane >> 4) * 8;
                uint32_t ad = (uint32_t)__cvta_generic_to_shared(sA + row * AS_STRIDE + col);
                ldsm4(ah[mt], ad);
            }
            #pragma unroll
            for (int nt2 = 0; nt2 < 2; nt2++) {
                int row = k16 * 16 + (lane & 15);
                int col = wn + nt2 * 16 + ((lane >> 4) & 1) * 8;
                uint32_t t[4];
                uint32_t ad = (uint32_t)__cvta_generic_to_shared(sBhi + row * BS_STRIDE + col);
                ldsm4t(t, ad);
                bh[nt2 * 2][0] = t[0]; bh[nt2 * 2][1] = t[1];
                bh[nt2 * 2 + 1][0] = t[2]; bh[nt2 * 2 + 1][1] = t[3];
                ad = (uint32_t)__cvta_generic_to_shared(sBlo + row * BS_STRIDE + col);
                ldsm4t(t, ad);
                bl[nt2 * 2][0] = t[0]; bl[nt2 * 2][1] = t[1];
                bl[nt2 * 2 + 1][0] = t[2]; bl[nt2 * 2 + 1][1] = t[3];
            }
            #pragma unroll
            for (int mt = 0; mt < 5; mt++)
                #pragma unroll
                for (int nt = 0; nt < 4; nt++) {
                    mma16816f(acc[mt][nt], ah[mt], bh[nt]);
                    mma16816f(acc[mt][nt], ah[mt], bl[nt]);
                }
        }
        __syncthreads();
    }

    if (mode == 0) {
        #pragma unroll
        for (int mt = 0; mt < 5; mt++) {
            int r0 = m0 + wm + mt * 16 + (lane >> 2);
            int r1 = r0 + 8;
            float i0 = (r0 < NN) ? g_inv[r0] : 0.f;
            float i1 = (r1 < NN) ? g_inv[r1] : 0.f;
            #pragma unroll
            for (int nt = 0; nt < 4; nt++) {
                int cl = wn + nt * 8 + (lane & 3) * 2;
                float b0 = sbias[cl], b1 = sbias[cl + 1];
                float v0 = fmaxf(acc[mt][nt][0] + b0, 0.f) * i0;
                float v1 = fmaxf(acc[mt][nt][1] + b1, 0.f) * i0;
                float v2 = fmaxf(acc[mt][nt][2] + b0, 0.f) * i1;
                float v3 = fmaxf(acc[mt][nt][3] + b1, 0.f) * i1;
                if (r0 < NN) {
                    __half2 h = __floats2half2_rn(v0, v1);
                    *(uint32_t*)(XH + (size_t)r0 * 256 + n0 + cl) = *reinterpret_cast<uint32_t*>(&h);
                }
                if (r1 < NN) {
                    __half2 h = __floats2half2_rn(v2, v3);
                    *(uint32_t*)(XH + (size_t)r1 * 256 + n0 + cl) = *reinterpret_cast<uint32_t*>(&h);
                }
            }
        }
    } else {
        // layer-2 fused: y' partial = relu(x2).u ; V partial = relu(x2).t (deg>0)
        float wu[8], wt[8];
        #pragma unroll
        for (int nt = 0; nt < 4; nt++) {
            int cg = n0 + wn + nt * 8 + (lane & 3) * 2;
            wu[nt * 2] = g_u[cg]; wu[nt * 2 + 1] = g_u[cg + 1];
            wt[nt * 2] = g_t[cg]; wt[nt * 2 + 1] = g_t[cg + 1];
        }
        for (int i = tid; i < MT; i += 256) spi[i] = 0.f;
        __syncthreads();
        float vth = 0.f;
        #pragma unroll
        for (int mt = 0; mt < 5; mt++) {
            int r0 = m0 + wm + mt * 16 + (lane >> 2);
            int r1 = r0 + 8;
            float i0 = (r0 < NN) ? g_inv[r0] : 0.f;
            float i1 = (r1 < NN) ? g_inv[r1] : 0.f;
            float p0 = 0.f, p1 = 0.f, q0 = 0.f, q1 = 0.f;
            #pragma unroll
            for (int nt = 0; nt < 4; nt++) {
                int cl = wn + nt * 8 + (lane & 3) * 2;
                float b0 = sbias[cl], b1 = sbias[cl + 1];
                float v0 = fmaxf(acc[mt][nt][0] + b0, 0.f);
                float v1 = fmaxf(acc[mt][nt][1] + b1, 0.f);
                float v2 = fmaxf(acc[mt][nt][2] + b0, 0.f);
                float v3 = fmaxf(acc[mt][nt][3] + b1, 0.f);
                p0 += v0 * wu[nt * 2] + v1 * wu[nt * 2 + 1];
                p1 += v2 * wu[nt * 2] + v3 * wu[nt * 2 + 1];
                q0 += v0 * wt[nt * 2] + v1 * wt[nt * 2 + 1];
                q1 += v2 * wt[nt * 2] + v3 * wt[nt * 2 + 1];
            }
            #pragma unroll
            for (int o = 1; o <= 2; o <<= 1) {
                p0 += __shfl_xor_sync(0xffffffffu, p0, o);
                p1 += __shfl_xor_sync(0xffffffffu, p1, o);
                q0 += __shfl_xor_sync(0xffffffffu, q0, o);
                q1 += __shfl_xor_sync(0xffffffffu, q1, o);
            }
            if ((lane & 3) == 0) {
                int lr = wm + mt * 16 + (lane >> 2);
                atomicAdd(&spi[lr], p0);
                atomicAdd(&spi[lr + 8], p1);
                vth += (i0 > 0.f ? q0 : 0.f) + (i1 > 0.f ? q1 : 0.f);
            }
        }
        #pragma unroll
        for (int o = 16; o > 0; o >>= 1) vth += __shfl_xor_sync(0xffffffffu, vth, o);
        if (lane == 0) svred[wid] = vth;
        __syncthreads();
        for (int i = tid; i < MT; i += 256) {
            int gr = m0 + i;
            if (gr < NN) atomicAdd(&g_y[gr], spi[i] * g_inv[gr]);
        }
        if (tid == 0) {
            float s = 0.f;
            #pragma unroll
            for (int w = 0; w < 8; w++) s += svred[w];
            atomicAdd(&g_vsum, s);
        }
    }
}

// ---------------- PI: scalar aggregation of y' over in-edges + final V write ----------------
__global__ void pi_kernel(const float* __restrict__ bv, float* __restrict__ out) {
    int gw   = (blockIdx.x * blockDim.x + threadIdx.x) >> 5;
    int lane = threadIdx.x & 31;
    int nwrp = (gridDim.x * blockDim.x) >> 5;
    for (int n = gw; n < NN; n += nwrp) {
        int s0 = g_roff[n], s1 = g_rend[n];
        float sum = 0.f;
        for (int e = s0 + lane; e < s1; e += 32)
            sum += g_y[g_csr[e]];
        #pragma unroll
        for (int o = 16; o > 0; o >>= 1)
            sum += __shfl_xor_sync(0xffffffffu, sum, o);
        if (lane == 0) out[n] += sum;
    }
    if (blockIdx.x == 0 && threadIdx.x == 0) {
        out[NN] = g_vsum * (1.0f / (float)NN) + g_dotv + bv[0];
        g_total = 0;   // restore invariant for next run
    }
}

// ---------------- launch ----------------
extern "C" void kernel_launch(void* const* d_in, const int* in_sizes, int n_in,
                              void* d_out, int out_size) {
    const float* features = (const float*)d_in[0];
    const int*   src      = (const int*)d_in[1];
    const int*   dst      = (const int*)d_in[2];
    const float* W1 = (const float*)d_in[3];
    const float* b1 = (const float*)d_in[4];
    const float* W2 = (const float*)d_in[5];
    const float* b2 = (const float*)d_in[6];
    const float* W3 = (const float*)d_in[7];
    const float* b3 = (const float*)d_in[8];
    const float* Wp = (const float*)d_in[9];
    const float* bp = (const float*)d_in[10];
    const float* Wv = (const float*)d_in[11];
    const float* bv = (const float*)d_in[12];
    float* out = (float*)d_out;

    void *pXH_, *pAgg_, *pWhi_, *pWlo_;
    cudaGetSymbolAddress(&pXH_, g_x16);
    cudaGetSymbolAddress(&pAgg_, g_agg16);
    cudaGetSymbolAddress(&pWhi_, g_whi);
    cudaGetSymbolAddress(&pWlo_, g_wlo);
    __half* xh = (__half*)pXH_;
    __half* agg16 = (__half*)pAgg_;
    __half* whi = (__half*)pWhi_;
    __half* wlo = (__half*)pWlo_;

    // preprocessing
    count_conv_kernel<<<(CC_TOTAL + 255) / 256, 256>>>(src, dst, W1, W2, W3, b3, Wp, Wv);
    alloc_kernel<<<(NN + 255) / 256, 256>>>(bp, out);
    int fl_threads = EPT_T + NFP;
    fill_kernel<<<(fl_threads + 255) / 256, 256>>>(src, dst, features);

    dim3 ggrid((NN + MT - 1) / MT, 2);  // 63 x 2 = 126 CTAs

    // layer 1 (K=128)
    aggregate_kernel<1><<<1250, 256>>>(xh, agg16, 128);
    gemm_mma<<<ggrid, 256>>>(agg16, whi, wlo, b1, xh, 128, 0);
    // layer 2 (K=256): fused exact layer-3 shortcut (y', V partials)
    aggregate_kernel<2><<<1250, 256>>>(xh, agg16, 256);
    gemm_mma<<<ggrid, 256>>>(agg16, whi + 32768, wlo + 32768, b2, xh, 256, 2);
    // PI scalar aggregation + V finalize
    pi_kernel<<<1250, 256>>>(bv, out);
}